// round 10
// baseline (speedup 1.0000x reference)
#include <cuda_runtime.h>
#include <cuda_fp16.h>
#include <cstdint>

#define NODES 50000
#define EDGES 800000
#define HID   128
#define NLAYER 3

// ---------------- scratch (static device globals; no allocation) ----------------
__device__ __half g_xh [NODES * HID];      // node state, fp16
__device__ float  g_p  [NODES * HID];      // P per node (fp32)
__device__ __half g_qh [NODES * HID];      // Q per node (fp16, gathered per edge)
__device__ __half g_Hh [NODES * HID];      // inv_deg * segment_sum(relu_h), fp16
__device__ int2  g_edge[EDGES];            // {src, ea bits}
__device__ int   g_deg [NODES];
__device__ int   g_tmp [NODES];
__device__ int   g_rowptr[NODES + 1];
__device__ int   g_cursor[NODES];
__device__ float g_invdeg[NODES];
__device__ float g_gate  [NODES];
__device__ __half g_wTh[NLAYER * 5 * HID * HID];  // B^T fp16: 0=W1a 1=W1b 2=U1a 3=U2 4=Wc
__device__ float g_bc  [NLAYER * HID];            // b2 @ U1b per layer
__device__ float g_gvec[HID];
__device__ int   g_is64;
__device__ int   g_bsum[64];

// ================= helpers =================
__device__ __forceinline__ void mma16(float* c, const uint32_t* a, const uint32_t* b) {
    asm volatile(
        "mma.sync.aligned.m16n8k16.row.col.f32.f16.f16.f32 "
        "{%0,%1,%2,%3},{%4,%5,%6,%7},{%8,%9},{%0,%1,%2,%3};"
        : "+f"(c[0]), "+f"(c[1]), "+f"(c[2]), "+f"(c[3])
        : "r"(a[0]), "r"(a[1]), "r"(a[2]), "r"(a[3]), "r"(b[0]), "r"(b[1]));
}
__device__ __forceinline__ void ldm_x4(uint32_t* r, uint32_t saddr) {
    asm volatile("ldmatrix.sync.aligned.m8n8.x4.shared.b16 {%0,%1,%2,%3}, [%4];"
        : "=r"(r[0]), "=r"(r[1]), "=r"(r[2]), "=r"(r[3]) : "r"(saddr));
}

// ================= CSR build =================
__global__ void k_init(const int* __restrict__ ei, int N) {
    int i = blockIdx.x * blockDim.x + threadIdx.x;
    if (i < N) g_deg[i] = 0;
    if (i < 128) g_gvec[i] = 0.0f;
    if (i == 0) {
        int z = 1;
        #pragma unroll
        for (int k = 1; k < 16; k += 2) if (ei[k] != 0) z = 0;
        g_is64 = z;
    }
}
__global__ void k_count(const int* __restrict__ ei, int E) {
    int e = blockIdx.x * blockDim.x + threadIdx.x;
    if (e >= E) return;
    int is64 = g_is64;
    int dst = is64 ? ei[2 * E + 2 * e] : ei[E + e];
    atomicAdd(&g_deg[dst], 1);
}
__global__ void k_scan1(int N) {
    __shared__ int s[1024];
    int tid = threadIdx.x;
    int i = blockIdx.x * 1024 + tid;
    int v = (i < N) ? g_deg[i] : 0;
    s[tid] = v;
    __syncthreads();
    for (int off = 1; off < 1024; off <<= 1) {
        int t = (tid >= off) ? s[tid - off] : 0;
        __syncthreads();
        s[tid] += t;
        __syncthreads();
    }
    if (i < N) g_tmp[i] = s[tid];
    if (tid == 1023) g_bsum[blockIdx.x] = s[1023];
}
__global__ void k_scan3(int N) {
    __shared__ int sred[64];
    int tid = threadIdx.x;
    int blk = (blockIdx.x * 256) >> 10;
    if (tid < 64) sred[tid] = (tid < blk) ? g_bsum[tid] : 0;
    __syncthreads();
    #pragma unroll
    for (int off = 32; off > 0; off >>= 1) {
        if (tid < off) sred[tid] += sred[tid + off];
        __syncthreads();
    }
    int boff = sred[0];
    int i = blockIdx.x * 256 + tid;
    if (i >= N) return;
    int incl = g_tmp[i] + boff;
    int d = g_deg[i];
    int excl = incl - d;
    g_rowptr[i] = excl;
    g_cursor[i] = excl;
    g_invdeg[i] = 1.0f / fmaxf((float)d, 1.0f);
    g_gate[i]   = (d > 0) ? 1.0f : 0.0f;
    if (i == N - 1) g_rowptr[N] = incl;
}
__global__ void k_scatter(const int* __restrict__ ei, const float* __restrict__ ea, int E) {
    int e = blockIdx.x * blockDim.x + threadIdx.x;
    if (e >= E) return;
    int is64 = g_is64;
    int src = is64 ? ei[2 * e]         : ei[e];
    int dst = is64 ? ei[2 * E + 2 * e] : ei[E + e];
    int pos = atomicAdd(&g_cursor[dst], 1);
    g_edge[pos] = make_int2(src, __float_as_int(ea[e]));
}

// ================= encoder =================
__global__ void k_encode(const float* __restrict__ nf, const float* __restrict__ W,
                         const float* __restrict__ b, int N) {
    int t = blockIdx.x * blockDim.x + threadIdx.x;
    if (t >= N * HID) return;
    int n = t >> 7, c = t & 127;
    float acc = b[c];
    #pragma unroll
    for (int k = 0; k < 5; k++) acc = fmaf(nf[n * 5 + k], W[k * HID + c], acc);
    g_xh[t] = __float2half_rn(acc);
}

// ================= weight repack (ALL layers, transpose, to fp16) =================
__global__ void k_repackT(const float* __restrict__ mlp_W1, const float* __restrict__ upd_W1,
                          const float* __restrict__ upd_W2) {
    int t = blockIdx.x * blockDim.x + threadIdx.x;
    int l = t / (4 * 16384);
    int r = t % (4 * 16384);
    int w = r >> 14;
    int j = (r >> 7) & 127;
    int k = r & 127;
    const float* W1 = mlp_W1 + (size_t)l * 257 * 128;
    const float* U1 = upd_W1 + (size_t)l * 256 * 128;
    const float* U2 = upd_W2 + (size_t)l * 128 * 128;
    float v;
    switch (w) {
        case 0:  v = W1[k * 128 + j];          break;
        case 1:  v = W1[(128 + k) * 128 + j];  break;
        case 2:  v = U1[k * 128 + j];          break;
        default: v = U2[k * 128 + j];          break;
    }
    g_wTh[(size_t)l * 5 * 16384 + (size_t)w * 16384 + j * 128 + k] = __float2half_rn(v);
}

// ================= fused small weight: Wc = W2 @ U1b, bc = b2 @ U1b =================
__global__ void k_fuseW(const float* __restrict__ mlp_W2, const float* __restrict__ upd_W1,
                        const float* __restrict__ mlp_b2) {
    __shared__ float w2row[128];
    int k = blockIdx.x, l = blockIdx.y, j = threadIdx.x;
    const float* W2 = mlp_W2 + (size_t)l * 128 * 128;
    const float* U1 = upd_W1 + (size_t)l * 256 * 128;
    const float* b2 = mlp_b2 + l * 128;
    w2row[j] = W2[k * 128 + j];
    __syncthreads();
    float acc = 0.f;
    #pragma unroll 8
    for (int t = 0; t < 128; t++) acc = fmaf(w2row[t], U1[(128 + t) * 128 + j], acc);
    g_wTh[(size_t)l * 5 * 16384 + 4 * 16384 + j * 128 + k] = __float2half_rn(acc);
    if (k == 0) {
        float bacc = 0.f;
        #pragma unroll 8
        for (int t = 0; t < 128; t++) bacc = fmaf(b2[t], U1[(128 + t) * 128 + j], bacc);
        g_bc[l * 128 + j] = bacc;
    }
}

// ================= fp16 mma.sync GEMMs: 64x128 CTA tile, 8 warps (2m x 4n) =================
#define STR  72
#define STRT 136
#define PQ_SMEM_BYTES   ((64 + 128) * STR * 2)
#define UPD_SMEM_BYTES  (((64 + 128) * STR + 64 * STRT) * 2)

// ---- layer-0 PQ kernel: y=0 -> P = x@W1a^T + b1 (fp32); y=1 -> Q = x@W1b^T (fp16) ----
__global__ void __launch_bounds__(256, 3)
k_gemm_pq(const __half* __restrict__ A1,
          const __half* __restrict__ B1, const __half* __restrict__ B2,
          const float* __restrict__ bias,
          float* __restrict__ Cf, __half* __restrict__ Ch, int M)
{
    extern __shared__ __half smh[];
    __half* As = smh;
    __half* Bs = smh + 64 * STR;

    const int tid = threadIdx.x;
    const int wid = tid >> 5, lane = tid & 31;
    const int g = lane >> 2, tig = lane & 3;
    const int lt = lane >> 3, lw = lane & 7;
    const int warp_m = wid >> 2, warp_n = wid & 3;
    const int mw = warp_m * 32, nw = warp_n * 32;
    const int m0 = blockIdx.x * 64;
    const __half* B = (blockIdx.y == 0) ? B1 : B2;

    uint32_t aBase[2], bBase[2];
    #pragma unroll
    for (int i = 0; i < 2; i++)
        aBase[i] = (uint32_t)__cvta_generic_to_shared(
            &As[(mw + i * 16 + (lt & 1) * 8 + lw) * STR + (lt >> 1) * 8]);
    #pragma unroll
    for (int jj = 0; jj < 2; jj++)
        bBase[jj] = (uint32_t)__cvta_generic_to_shared(
            &Bs[(nw + jj * 16 + (lt >> 1) * 8 + lw) * STR + (lt & 1) * 8]);

    float acc[2][4][4];
    #pragma unroll
    for (int i = 0; i < 2; i++)
        #pragma unroll
        for (int j = 0; j < 4; j++)
            #pragma unroll
            for (int r = 0; r < 4; r++) acc[i][j][r] = 0.0f;

    for (int c = 0; c < 2; c++) {
        __syncthreads();
        #pragma unroll
        for (int u = 0; u < 2; u++) {
            int linear = u * 256 + tid;
            int row = linear >> 3, q = linear & 7;
            uint4 av = make_uint4(0u, 0u, 0u, 0u);
            if (m0 + row < M)
                av = *(const uint4*)&A1[(size_t)(m0 + row) * 128 + c * 64 + q * 8];
            *(uint4*)&As[row * STR + q * 8] = av;
        }
        #pragma unroll
        for (int u = 0; u < 4; u++) {
            int linear = u * 256 + tid;
            int row = linear >> 3, q = linear & 7;
            *(uint4*)&Bs[row * STR + q * 8] =
                *(const uint4*)&B[(size_t)row * 128 + c * 64 + q * 8];
        }
        __syncthreads();
        #pragma unroll
        for (int ks = 0; ks < 4; ks++) {
            const int k0 = ks * 16;
            uint32_t af[2][4], bf[2][4];
            ldm_x4(af[0], aBase[0] + k0 * 2);
            ldm_x4(af[1], aBase[1] + k0 * 2);
            ldm_x4(bf[0], bBase[0] + k0 * 2);
            ldm_x4(bf[1], bBase[1] + k0 * 2);
            #pragma unroll
            for (int i = 0; i < 2; i++)
                #pragma unroll
                for (int jj = 0; jj < 2; jj++)
                    #pragma unroll
                    for (int jo = 0; jo < 2; jo++)
                        mma16(acc[i][jj * 2 + jo], af[i], &bf[jj][jo * 2]);
        }
    }

    float bcol[4][2];
    #pragma unroll
    for (int j = 0; j < 4; j++) {
        int col = nw + j * 8 + 2 * tig;
        bool haveb = (blockIdx.y == 0);
        bcol[j][0] = haveb ? bias[col]     : 0.0f;
        bcol[j][1] = haveb ? bias[col + 1] : 0.0f;
    }
    #pragma unroll
    for (int i = 0; i < 2; i++) {
        #pragma unroll
        for (int h = 0; h < 2; h++) {
            int row = m0 + mw + i * 16 + g + 8 * h;
            if (row >= M) continue;
            #pragma unroll
            for (int j = 0; j < 4; j++) {
                int col = nw + j * 8 + 2 * tig;
                float v0 = acc[i][j][2 * h] + bcol[j][0];
                float v1 = acc[i][j][2 * h + 1] + bcol[j][1];
                if (blockIdx.y == 0) {
                    float2 o; o.x = v0; o.y = v1;
                    *(float2*)&Cf[(size_t)row * 128 + col] = o;
                } else {
                    *(__half2*)&Ch[(size_t)row * 128 + col] = __floats2half2_rn(v0, v1);
                }
            }
        }
    }
}

// ---- fused UPD + LN (+ next-layer PQ, or readout mean) ----
template<int TAIL>
__global__ void __launch_bounds__(256, 3)
k_updln(const __half* __restrict__ A1, const __half* __restrict__ A2,
        const __half* __restrict__ B1, const __half* __restrict__ B2,
        const __half* __restrict__ B3,
        const __half* __restrict__ B4, const __half* __restrict__ B5,
        const float* __restrict__ bias, const float* __restrict__ bias2,
        const float* __restrict__ rowgate,
        const float* __restrict__ biasln,
        const float* __restrict__ lng, const float* __restrict__ lnb,
        const float* __restrict__ bP,
        __half* __restrict__ Ch, float* __restrict__ Pf, __half* __restrict__ Qh, int M)
{
    extern __shared__ __half smh[];
    __half* As = smh;                        // [64][72]
    __half* Bs = smh + 64 * STR;             // [128][72]
    __half* T  = smh + (64 + 128) * STR;     // [64][136]

    const int tid = threadIdx.x;
    const int wid = tid >> 5, lane = tid & 31;
    const int g = lane >> 2, tig = lane & 3;
    const int lt = lane >> 3, lw = lane & 7;
    const int warp_m = wid >> 2, warp_n = wid & 3;
    const int mw = warp_m * 32, nw = warp_n * 32;
    const int m0 = blockIdx.x * 64;

    uint32_t aBase[2], bBase[2], tBase[2];
    #pragma unroll
    for (int i = 0; i < 2; i++) {
        aBase[i] = (uint32_t)__cvta_generic_to_shared(
            &As[(mw + i * 16 + (lt & 1) * 8 + lw) * STR + (lt >> 1) * 8]);
        tBase[i] = (uint32_t)__cvta_generic_to_shared(
            &T[(mw + i * 16 + (lt & 1) * 8 + lw) * STRT + (lt >> 1) * 8]);
    }
    #pragma unroll
    for (int jj = 0; jj < 2; jj++)
        bBase[jj] = (uint32_t)__cvta_generic_to_shared(
            &Bs[(nw + jj * 16 + (lt >> 1) * 8 + lw) * STR + (lt & 1) * 8]);

    float acc[2][4][4];
    #pragma unroll
    for (int i = 0; i < 2; i++)
        #pragma unroll
        for (int j = 0; j < 4; j++)
            #pragma unroll
            for (int r = 0; r < 4; r++) acc[i][j][r] = 0.0f;

    // ---- phase 1: dual-input GEMM ----
    for (int p = 0; p < 2; p++) {
        const __half* A = p ? A2 : A1;
        const __half* B = p ? B2 : B1;
        for (int c = 0; c < 2; c++) {
            __syncthreads();
            #pragma unroll
            for (int u = 0; u < 2; u++) {
                int linear = u * 256 + tid;
                int row = linear >> 3, q = linear & 7;
                uint4 av = make_uint4(0u, 0u, 0u, 0u);
                if (m0 + row < M)
                    av = *(const uint4*)&A[(size_t)(m0 + row) * 128 + c * 64 + q * 8];
                *(uint4*)&As[row * STR + q * 8] = av;
            }
            #pragma unroll
            for (int u = 0; u < 4; u++) {
                int linear = u * 256 + tid;
                int row = linear >> 3, q = linear & 7;
                *(uint4*)&Bs[row * STR + q * 8] =
                    *(const uint4*)&B[(size_t)row * 128 + c * 64 + q * 8];
            }
            __syncthreads();
            #pragma unroll
            for (int ks = 0; ks < 4; ks++) {
                const int k0 = ks * 16;
                uint32_t af[2][4], bf[2][4];
                ldm_x4(af[0], aBase[0] + k0 * 2);
                ldm_x4(af[1], aBase[1] + k0 * 2);
                ldm_x4(bf[0], bBase[0] + k0 * 2);
                ldm_x4(bf[1], bBase[1] + k0 * 2);
                #pragma unroll
                for (int i = 0; i < 2; i++)
                    #pragma unroll
                    for (int jj = 0; jj < 2; jj++)
                        #pragma unroll
                        for (int jo = 0; jo < 2; jo++)
                            mma16(acc[i][jj * 2 + jo], af[i], &bf[jj][jo * 2]);
            }
        }
    }

    // ---- epilogue 1: t -> smem T ----
    {
        float bcol[4][2], b2col[4][2];
        #pragma unroll
        for (int j = 0; j < 4; j++) {
            int col = nw + j * 8 + 2 * tig;
            bcol[j][0]  = bias[col];      bcol[j][1]  = bias[col + 1];
            b2col[j][0] = bias2[col];     b2col[j][1] = bias2[col + 1];
        }
        #pragma unroll
        for (int i = 0; i < 2; i++) {
            #pragma unroll
            for (int h = 0; h < 2; h++) {
                int rl = mw + i * 16 + g + 8 * h;
                int row = m0 + rl;
                float gt = (row < M) ? rowgate[row] : 0.f;
                #pragma unroll
                for (int j = 0; j < 4; j++) {
                    int col = nw + j * 8 + 2 * tig;
                    float v0 = fmaxf(acc[i][j][2*h]   + bcol[j][0] + gt * b2col[j][0], 0.f);
                    float v1 = fmaxf(acc[i][j][2*h+1] + bcol[j][1] + gt * b2col[j][1], 0.f);
                    *(__half2*)&T[rl * STRT + col] = __floats2half2_rn(v0, v1);
                }
            }
        }
    }
    #pragma unroll
    for (int i = 0; i < 2; i++)
        #pragma unroll
        for (int j = 0; j < 4; j++)
            #pragma unroll
            for (int r = 0; r < 4; r++) acc[i][j][r] = 0.0f;

    // ---- phase 2: t @ U2^T (A from smem T) ----
    for (int c = 0; c < 2; c++) {
        __syncthreads();
        #pragma unroll
        for (int u = 0; u < 4; u++) {
            int linear = u * 256 + tid;
            int row = linear >> 3, q = linear & 7;
            *(uint4*)&Bs[row * STR + q * 8] =
                *(const uint4*)&B3[(size_t)row * 128 + c * 64 + q * 8];
        }
        __syncthreads();
        #pragma unroll
        for (int ks = 0; ks < 4; ks++) {
            const int kT = (c * 64 + ks * 16) * 2;
            const int kB = (ks * 16) * 2;
            uint32_t af[2][4], bf[2][4];
            ldm_x4(af[0], tBase[0] + kT);
            ldm_x4(af[1], tBase[1] + kT);
            ldm_x4(bf[0], bBase[0] + kB);
            ldm_x4(bf[1], bBase[1] + kB);
            #pragma unroll
            for (int i = 0; i < 2; i++)
                #pragma unroll
                for (int jj = 0; jj < 2; jj++)
                    #pragma unroll
                    for (int jo = 0; jo < 2; jo++)
                        mma16(acc[i][jj * 2 + jo], af[i], &bf[jj][jo * 2]);
        }
    }

    // ---- LN epilogue ----
    float csum[4][2];
    #pragma unroll
    for (int j = 0; j < 4; j++) { csum[j][0] = 0.f; csum[j][1] = 0.f; }
    {
        __syncthreads();
        float* sS  = (float*)As;
        float* sS2 = (float*)As + 256;
        float bcol[4][2], gcol[4][2], lcol[4][2];
        #pragma unroll
        for (int j = 0; j < 4; j++) {
            int col = nw + j * 8 + 2 * tig;
            bcol[j][0] = biasln[col];  bcol[j][1] = biasln[col + 1];
            gcol[j][0] = lng[col];     gcol[j][1] = lng[col + 1];
            lcol[j][0] = lnb[col];     lcol[j][1] = lnb[col + 1];
        }
        #pragma unroll
        for (int i = 0; i < 2; i++) {
            #pragma unroll
            for (int h = 0; h < 2; h++) {
                float s = 0.f, s2 = 0.f;
                #pragma unroll
                for (int j = 0; j < 4; j++) {
                    #pragma unroll
                    for (int r = 0; r < 2; r++) {
                        float v = acc[i][j][2 * h + r] + bcol[j][r];
                        s += v; s2 += v * v;
                    }
                }
                s  += __shfl_xor_sync(0xffffffffu, s, 1);
                s  += __shfl_xor_sync(0xffffffffu, s, 2);
                s2 += __shfl_xor_sync(0xffffffffu, s2, 1);
                s2 += __shfl_xor_sync(0xffffffffu, s2, 2);
                if (tig == 0) {
                    int rl = mw + i * 16 + g + 8 * h;
                    sS [rl * 4 + warp_n] = s;
                    sS2[rl * 4 + warp_n] = s2;
                }
            }
        }
        __syncthreads();
        #pragma unroll
        for (int i = 0; i < 2; i++) {
            #pragma unroll
            for (int h = 0; h < 2; h++) {
                int rl = mw + i * 16 + g + 8 * h;
                int row = m0 + rl;
                float s  = sS [rl * 4] + sS [rl * 4 + 1] + sS [rl * 4 + 2] + sS [rl * 4 + 3];
                float s2 = sS2[rl * 4] + sS2[rl * 4 + 1] + sS2[rl * 4 + 2] + sS2[rl * 4 + 3];
                float mu   = s * (1.0f / 128.0f);
                float var  = s2 * (1.0f / 128.0f) - mu * mu;
                float rstd = rsqrtf(var + 1e-5f);
                #pragma unroll
                for (int j = 0; j < 4; j++) {
                    int col = nw + j * 8 + 2 * tig;
                    float v0 = fmaxf((acc[i][j][2*h]   + bcol[j][0] - mu) * rstd * gcol[j][0] + lcol[j][0], 0.f);
                    float v1 = fmaxf((acc[i][j][2*h+1] + bcol[j][1] - mu) * rstd * gcol[j][1] + lcol[j][1], 0.f);
                    __half2 hv = __floats2half2_rn(v0, v1);
                    if constexpr (TAIL == 1) *(__half2*)&T[rl * STRT + col] = hv;
                    if (row < M) {
                        if constexpr (TAIL != 2) *(__half2*)&Ch[(size_t)row * 128 + col] = hv;
                        if constexpr (TAIL == 2) { csum[j][0] += v0; csum[j][1] += v1; }
                    }
                }
            }
        }
    }

    if constexpr (TAIL == 2) {
        __syncthreads();
        float* sgv = (float*)Bs;
        if (tid < 128) sgv[tid] = 0.f;
        __syncthreads();
        #pragma unroll
        for (int j = 0; j < 4; j++) {
            int col = nw + j * 8 + 2 * tig;
            atomicAdd(&sgv[col],     csum[j][0]);
            atomicAdd(&sgv[col + 1], csum[j][1]);
        }
        __syncthreads();
        if (tid < 128) atomicAdd(&g_gvec[tid], sgv[tid]);
    }

    if constexpr (TAIL == 1) {
        __syncthreads();
        #pragma unroll
        for (int pq = 0; pq < 2; pq++) {
            const __half* B = pq ? B5 : B4;
            #pragma unroll
            for (int i = 0; i < 2; i++)
                #pragma unroll
                for (int j = 0; j < 4; j++)
                    #pragma unroll
                    for (int r = 0; r < 4; r++) acc[i][j][r] = 0.0f;
            for (int c = 0; c < 2; c++) {
                __syncthreads();
                #pragma unroll
                for (int u = 0; u < 4; u++) {
                    int linear = u * 256 + tid;
                    int row = linear >> 3, q = linear & 7;
                    *(uint4*)&Bs[row * STR + q * 8] =
                        *(const uint4*)&B[(size_t)row * 128 + c * 64 + q * 8];
                }
                __syncthreads();
                #pragma unroll
                for (int ks = 0; ks < 4; ks++) {
                    const int kT = (c * 64 + ks * 16) * 2;
                    const int kB = (ks * 16) * 2;
                    uint32_t af[2][4], bf[2][4];
                    ldm_x4(af[0], tBase[0] + kT);
                    ldm_x4(af[1], tBase[1] + kT);
                    ldm_x4(bf[0], bBase[0] + kB);
                    ldm_x4(bf[1], bBase[1] + kB);
                    #pragma unroll
                    for (int i = 0; i < 2; i++)
                        #pragma unroll
                        for (int jj = 0; jj < 2; jj++)
                            #pragma unroll
                            for (int jo = 0; jo < 2; jo++)
                                mma16(acc[i][jj * 2 + jo], af[i], &bf[jj][jo * 2]);
                }
            }
            if (pq == 0) {
                float bq[4][2];
                #pragma unroll
                for (int j = 0; j < 4; j++) {
                    int col = nw + j * 8 + 2 * tig;
                    bq[j][0] = bP[col]; bq[j][1] = bP[col + 1];
                }
                #pragma unroll
                for (int i = 0; i < 2; i++) {
                    #pragma unroll
                    for (int h = 0; h < 2; h++) {
                        int row = m0 + mw + i * 16 + g + 8 * h;
                        if (row >= M) continue;
                        #pragma unroll
                        for (int j = 0; j < 4; j++) {
                            int col = nw + j * 8 + 2 * tig;
                            float2 o;
                            o.x = acc[i][j][2 * h]     + bq[j][0];
                            o.y = acc[i][j][2 * h + 1] + bq[j][1];
                            *(float2*)&Pf[(size_t)row * 128 + col] = o;
                        }
                    }
                }
            } else {
                #pragma unroll
                for (int i = 0; i < 2; i++) {
                    #pragma unroll
                    for (int h = 0; h < 2; h++) {
                        int row = m0 + mw + i * 16 + g + 8 * h;
                        if (row >= M) continue;
                        #pragma unroll
                        for (int j = 0; j < 4; j++) {
                            int col = nw + j * 8 + 2 * tig;
                            *(__half2*)&Qh[(size_t)row * 128 + col] =
                                __floats2half2_rn(acc[i][j][2 * h], acc[i][j][2 * h + 1]);
                        }
                    }
                }
            }
        }
    }
}

// ================= edge aggregation: half-warp per edge, uint4 gather =================
__global__ void __launch_bounds__(256) k_aggr(const float* __restrict__ w1c, int N) {
    int warp = (blockIdx.x * blockDim.x + threadIdx.x) >> 5;
    int lane = threadIdx.x & 31;
    if (warp >= N) return;
    int node = warp;
    int half = lane >> 4, hl = lane & 15;
    float p[8], w[8];
    {
        float4 pa = *(const float4*)&g_p[(size_t)node * 128 + hl * 8];
        float4 pb = *(const float4*)&g_p[(size_t)node * 128 + hl * 8 + 4];
        float4 wa = *(const float4*)&w1c[hl * 8];
        float4 wb = *(const float4*)&w1c[hl * 8 + 4];
        p[0]=pa.x; p[1]=pa.y; p[2]=pa.z; p[3]=pa.w;
        p[4]=pb.x; p[5]=pb.y; p[6]=pb.z; p[7]=pb.w;
        w[0]=wa.x; w[1]=wa.y; w[2]=wa.z; w[3]=wa.w;
        w[4]=wb.x; w[5]=wb.y; w[6]=wb.z; w[7]=wb.w;
    }
    float acc[8] = {0.f, 0.f, 0.f, 0.f, 0.f, 0.f, 0.f, 0.f};
    int s0 = g_rowptr[node], s1 = g_rowptr[node + 1];
    int j = s0;
    #pragma unroll 2
    for (; j + 1 < s1; j += 2) {
        int2 e = __ldg(&g_edge[j + half]);
        float ea = __int_as_float(e.y);
        uint4 r = *(const uint4*)&g_qh[(size_t)e.x * 128 + hl * 8];
        float2 q0 = __half22float2(*(const __half2*)&r.x);
        float2 q1 = __half22float2(*(const __half2*)&r.y);
        float2 q2 = __half22float2(*(const __half2*)&r.z);
        float2 q3 = __half22float2(*(const __half2*)&r.w);
        acc[0] += fmaxf(fmaf(ea, w[0], p[0] + q0.x), 0.f);
        acc[1] += fmaxf(fmaf(ea, w[1], p[1] + q0.y), 0.f);
        acc[2] += fmaxf(fmaf(ea, w[2], p[2] + q1.x), 0.f);
        acc[3] += fmaxf(fmaf(ea, w[3], p[3] + q1.y), 0.f);
        acc[4] += fmaxf(fmaf(ea, w[4], p[4] + q2.x), 0.f);
        acc[5] += fmaxf(fmaf(ea, w[5], p[5] + q2.y), 0.f);
        acc[6] += fmaxf(fmaf(ea, w[6], p[6] + q3.x), 0.f);
        acc[7] += fmaxf(fmaf(ea, w[7], p[7] + q3.y), 0.f);
    }
    if (j < s1 && half == 0) {
        int2 e = __ldg(&g_edge[j]);
        float ea = __int_as_float(e.y);
        uint4 r = *(const uint4*)&g_qh[(size_t)e.x * 128 + hl * 8];
        float2 q0 = __half22float2(*(const __half2*)&r.x);
        float2 q1 = __half22float2(*(const __half2*)&r.y);
        float2 q2 = __half22float2(*(const __half2*)&r.z);
        float2 q3 = __half22float2(*(const __half2*)&r.w);
        acc[0] += fmaxf(fmaf(ea, w[0], p[0] + q0.x), 0.f);
        acc[1] += fmaxf(fmaf(ea, w[1], p[1] + q0.y), 0.f);
        acc[2] += fmaxf(fmaf(ea, w[2], p[2] + q1.x), 0.f);
        acc[3] += fmaxf(fmaf(ea, w[3], p[3] + q1.y), 0.f);
        acc[4] += fmaxf(fmaf(ea, w[4], p[4] + q2.x), 0.f);
        acc[5] += fmaxf(fmaf(ea, w[5], p[5] + q2.y), 0.f);
        acc[6] += fmaxf(fmaf(ea, w[6], p[6] + q3.x), 0.f);
        acc[7] += fmaxf(fmaf(ea, w[7], p[7] + q3.y), 0.f);
    }
    #pragma unroll
    for (int i = 0; i < 8; i++)
        acc[i] += __shfl_down_sync(0xffffffffu, acc[i], 16);
    if (half == 0) {
        float inv = g_invdeg[node];
        __half2 h0 = __floats2half2_rn(acc[0] * inv, acc[1] * inv);
        __half2 h1 = __floats2half2_rn(acc[2] * inv, acc[3] * inv);
        __half2 h2 = __floats2half2_rn(acc[4] * inv, acc[5] * inv);
        __half2 h3 = __floats2half2_rn(acc[6] * inv, acc[7] * inv);
        uint4 u;
        u.x = *(uint32_t*)&h0; u.y = *(uint32_t*)&h1;
        u.z = *(uint32_t*)&h2; u.w = *(uint32_t*)&h3;
        *(uint4*)&g_Hh[(size_t)node * 128 + hl * 8] = u;
    }
}

// ================= readout =================
__global__ void k_out(const float* __restrict__ W1, const float* __restrict__ b1,
                      const float* __restrict__ W2, const float* __restrict__ b2,
                      float* __restrict__ out, float invN) {
    __shared__ float gs[128];
    __shared__ float hs[128];
    int c = threadIdx.x;
    gs[c] = g_gvec[c] * invN;
    __syncthreads();
    float a = b1[c];
    #pragma unroll 8
    for (int k = 0; k < 128; k++) a = fmaf(gs[k], W1[k * 128 + c], a);
    hs[c] = fmaxf(a, 0.0f);
    __syncthreads();
    float o = b2[c];
    #pragma unroll 8
    for (int k = 0; k < 128; k++) o = fmaf(hs[k], W2[k * 128 + c], o);
    out[c] = o;
}

// ================= launch =================
extern "C" void kernel_launch(void* const* d_in, const int* in_sizes, int n_in,
                              void* d_out, int out_size) {
    const float* node_feat = (const float*)d_in[0];
    const float* edge_attr = (const float*)d_in[1];
    const float* enc_W  = (const float*)d_in[2];
    const float* enc_b  = (const float*)d_in[3];
    const float* mlp_W1 = (const float*)d_in[4];
    const float* mlp_b1 = (const float*)d_in[5];
    const float* mlp_W2 = (const float*)d_in[6];
    const float* mlp_b2 = (const float*)d_in[7];
    const float* upd_W1 = (const float*)d_in[8];
    const float* upd_b1 = (const float*)d_in[9];
    const float* upd_W2 = (const float*)d_in[10];
    const float* upd_b2 = (const float*)d_in[11];
    const float* ln_g   = (const float*)d_in[12];
    const float* ln_b   = (const float*)d_in[13];
    const float* out_W1 = (const float*)d_in[14];
    const float* out_b1 = (const float*)d_in[15];
    const float* out_W2 = (const float*)d_in[16];
    const float* out_b2 = (const float*)d_in[17];
    const int*   ei     = (const int*)d_in[18];

    const int N = NODES;
    const int E = EDGES;

    float *pp, *pbc, *pgate;
    __half *pxh, *pqh, *pHh, *pwTh;
    cudaGetSymbolAddress((void**)&pxh,   g_xh);
    cudaGetSymbolAddress((void**)&pp,    g_p);
    cudaGetSymbolAddress((void**)&pqh,   g_qh);
    cudaGetSymbolAddress((void**)&pHh,   g_Hh);
    cudaGetSymbolAddress((void**)&pwTh,  g_wTh);
    cudaGetSymbolAddress((void**)&pbc,   g_bc);
    cudaGetSymbolAddress((void**)&pgate, g_gate);

    cudaFuncSetAttribute(k_gemm_pq, cudaFuncAttributeMaxDynamicSharedMemorySize, PQ_SMEM_BYTES);
    cudaFuncSetAttribute(k_updln<1>, cudaFuncAttributeMaxDynamicSharedMemorySize, UPD_SMEM_BYTES);
    cudaFuncSetAttribute(k_updln<2>, cudaFuncAttributeMaxDynamicSharedMemorySize, UPD_SMEM_BYTES);

    // CSR build
    k_init<<<(N + 255) / 256, 256>>>(ei, N);
    k_count<<<(E + 255) / 256, 256>>>(ei, E);
    k_scan1<<<(N + 1023) / 1024, 1024>>>(N);
    k_scan3<<<(N + 255) / 256, 256>>>(N);
    k_scatter<<<(E + 255) / 256, 256>>>(ei, edge_attr, E);

    // encoder + weight prep
    k_encode<<<(N * HID + 255) / 256, 256>>>(node_feat, enc_W, enc_b, N);
    k_repackT<<<NLAYER * 4 * 16384 / 256, 256>>>(mlp_W1, upd_W1, upd_W2);
    k_fuseW<<<dim3(128, NLAYER), 128>>>(mlp_W2, upd_W1, mlp_b2);

    const int gt64 = (N + 63) / 64;

    // layer 0 PQ (from encoder x)
    k_gemm_pq<<<dim3(gt64, 2), 256, PQ_SMEM_BYTES>>>(
        pxh, pwTh + 0 * 16384, pwTh + 1 * 16384, mlp_b1, pp, pqh, N);

    for (int l = 0; l < NLAYER; l++) {
        const float* W1l = mlp_W1 + (size_t)l * 257 * 128;
        __half* wl = pwTh + (size_t)l * 5 * 16384;

        k_aggr<<<(N + 7) / 8, 256>>>(W1l + 256 * 128, N);

        if (l < NLAYER - 1) {
            __half* wn = pwTh + (size_t)(l + 1) * 5 * 16384;
            k_updln<1><<<gt64, 256, UPD_SMEM_BYTES>>>(
                pxh, pHh, wl + 2 * 16384, wl + 4 * 16384, wl + 3 * 16384,
                wn + 0 * 16384, wn + 1 * 16384,
                upd_b1 + l * 128, pbc + l * 128, pgate,
                upd_b2 + l * 128, ln_g + l * 128, ln_b + l * 128,
                mlp_b1 + (l + 1) * 128,
                pxh, pp, pqh, N);
        } else {
            k_updln<2><<<gt64, 256, UPD_SMEM_BYTES>>>(
                pxh, pHh, wl + 2 * 16384, wl + 4 * 16384, wl + 3 * 16384,
                nullptr, nullptr,
                upd_b1 + l * 128, pbc + l * 128, pgate,
                upd_b2 + l * 128, ln_g + l * 128, ln_b + l * 128,
                nullptr,
                pxh, pp, pqh, N);
        }
    }

    k_out<<<1, 128>>>(out_W1, out_b1, out_W2, out_b2, (float*)d_out, 1.0f / (float)N);
}

// round 11
// speedup vs baseline: 1.1548x; 1.1548x over previous
#include <cuda_runtime.h>
#include <cuda_fp16.h>
#include <cstdint>

#define NODES 50000
#define EDGES 800000
#define HID   128
#define NLAYER 3

// ---------------- scratch (static device globals; no allocation) ----------------
__device__ __half g_xh [NODES * HID];      // node state, fp16
__device__ __half g_ph [NODES * HID];      // P per node (fp16, b1 folded in)
__device__ __half g_qh [NODES * HID];      // Q per node (fp16, gathered per edge)
__device__ __half g_Hh [NODES * HID];      // inv_deg * segment_sum(relu_h), fp16
__device__ int2  g_edge[EDGES];            // {src, ea bits}
__device__ int   g_deg [NODES];
__device__ int   g_tmp [NODES];
__device__ int   g_rowptr[NODES + 1];
__device__ int   g_cursor[NODES];
__device__ float g_invdeg[NODES];
__device__ float g_gate  [NODES];
__device__ __half g_wTh[NLAYER * 5 * HID * HID];  // B^T fp16: 0=W1a 1=W1b 2=U1a 3=U2 4=Wc
__device__ float g_bc  [NLAYER * HID];            // b2 @ U1b per layer
__device__ float g_gvec[HID];
__device__ int   g_is64;
__device__ int   g_bsum[64];

// ================= helpers =================
__device__ __forceinline__ void mma16(float* c, const uint32_t* a, const uint32_t* b) {
    asm volatile(
        "mma.sync.aligned.m16n8k16.row.col.f32.f16.f16.f32 "
        "{%0,%1,%2,%3},{%4,%5,%6,%7},{%8,%9},{%0,%1,%2,%3};"
        : "+f"(c[0]), "+f"(c[1]), "+f"(c[2]), "+f"(c[3])
        : "r"(a[0]), "r"(a[1]), "r"(a[2]), "r"(a[3]), "r"(b[0]), "r"(b[1]));
}

// ================= CSR build =================
__global__ void k_init(const int* __restrict__ ei, int N) {
    int i = blockIdx.x * blockDim.x + threadIdx.x;
    if (i < N) g_deg[i] = 0;
    if (i < 128) g_gvec[i] = 0.0f;
    if (i == 0) {
        int z = 1;
        #pragma unroll
        for (int k = 1; k < 16; k += 2) if (ei[k] != 0) z = 0;
        g_is64 = z;
    }
}
__global__ void k_count(const int* __restrict__ ei, int E) {
    int e = blockIdx.x * blockDim.x + threadIdx.x;
    if (e >= E) return;
    int is64 = g_is64;
    int dst = is64 ? ei[2 * E + 2 * e] : ei[E + e];
    atomicAdd(&g_deg[dst], 1);
}
__global__ void k_scan1(int N) {
    __shared__ int s[1024];
    int tid = threadIdx.x;
    int i = blockIdx.x * 1024 + tid;
    int v = (i < N) ? g_deg[i] : 0;
    s[tid] = v;
    __syncthreads();
    for (int off = 1; off < 1024; off <<= 1) {
        int t = (tid >= off) ? s[tid - off] : 0;
        __syncthreads();
        s[tid] += t;
        __syncthreads();
    }
    if (i < N) g_tmp[i] = s[tid];
    if (tid == 1023) g_bsum[blockIdx.x] = s[1023];
}
__global__ void k_scan3(int N) {
    __shared__ int sred[64];
    int tid = threadIdx.x;
    int blk = (blockIdx.x * 256) >> 10;
    if (tid < 64) sred[tid] = (tid < blk) ? g_bsum[tid] : 0;
    __syncthreads();
    #pragma unroll
    for (int off = 32; off > 0; off >>= 1) {
        if (tid < off) sred[tid] += sred[tid + off];
        __syncthreads();
    }
    int boff = sred[0];
    int i = blockIdx.x * 256 + tid;
    if (i >= N) return;
    int incl = g_tmp[i] + boff;
    int d = g_deg[i];
    int excl = incl - d;
    g_rowptr[i] = excl;
    g_cursor[i] = excl;
    g_invdeg[i] = 1.0f / fmaxf((float)d, 1.0f);
    g_gate[i]   = (d > 0) ? 1.0f : 0.0f;
    if (i == N - 1) g_rowptr[N] = incl;
}
__global__ void k_scatter(const int* __restrict__ ei, const float* __restrict__ ea, int E) {
    int e = blockIdx.x * blockDim.x + threadIdx.x;
    if (e >= E) return;
    int is64 = g_is64;
    int src = is64 ? ei[2 * e]         : ei[e];
    int dst = is64 ? ei[2 * E + 2 * e] : ei[E + e];
    int pos = atomicAdd(&g_cursor[dst], 1);
    g_edge[pos] = make_int2(src, __float_as_int(ea[e]));
}

// ================= encoder =================
__global__ void k_encode(const float* __restrict__ nf, const float* __restrict__ W,
                         const float* __restrict__ b, int N) {
    int t = blockIdx.x * blockDim.x + threadIdx.x;
    if (t >= N * HID) return;
    int n = t >> 7, c = t & 127;
    float acc = b[c];
    #pragma unroll
    for (int k = 0; k < 5; k++) acc = fmaf(nf[n * 5 + k], W[k * HID + c], acc);
    g_xh[t] = __float2half_rn(acc);
}

// ================= weight repack (ALL layers, transpose, to fp16) =================
__global__ void k_repackT(const float* __restrict__ mlp_W1, const float* __restrict__ upd_W1,
                          const float* __restrict__ upd_W2) {
    int t = blockIdx.x * blockDim.x + threadIdx.x;
    int l = t / (4 * 16384);
    int r = t % (4 * 16384);
    int w = r >> 14;
    int j = (r >> 7) & 127;
    int k = r & 127;
    const float* W1 = mlp_W1 + (size_t)l * 257 * 128;
    const float* U1 = upd_W1 + (size_t)l * 256 * 128;
    const float* U2 = upd_W2 + (size_t)l * 128 * 128;
    float v;
    switch (w) {
        case 0:  v = W1[k * 128 + j];          break;
        case 1:  v = W1[(128 + k) * 128 + j];  break;
        case 2:  v = U1[k * 128 + j];          break;
        default: v = U2[k * 128 + j];          break;
    }
    g_wTh[(size_t)l * 5 * 16384 + (size_t)w * 16384 + j * 128 + k] = __float2half_rn(v);
}

// ================= fused small weight: Wc = W2 @ U1b, bc = b2 @ U1b =================
__global__ void k_fuseW(const float* __restrict__ mlp_W2, const float* __restrict__ upd_W1,
                        const float* __restrict__ mlp_b2) {
    __shared__ float w2row[128];
    int k = blockIdx.x, l = blockIdx.y, j = threadIdx.x;
    const float* W2 = mlp_W2 + (size_t)l * 128 * 128;
    const float* U1 = upd_W1 + (size_t)l * 256 * 128;
    const float* b2 = mlp_b2 + l * 128;
    w2row[j] = W2[k * 128 + j];
    __syncthreads();
    float acc = 0.f;
    #pragma unroll 8
    for (int t = 0; t < 128; t++) acc = fmaf(w2row[t], U1[(128 + t) * 128 + j], acc);
    g_wTh[(size_t)l * 5 * 16384 + 4 * 16384 + j * 128 + k] = __float2half_rn(acc);
    if (k == 0) {
        float bacc = 0.f;
        #pragma unroll 8
        for (int t = 0; t < 128; t++) bacc = fmaf(b2[t], U1[(128 + t) * 128 + j], bacc);
        g_bc[l * 128 + j] = bacc;
    }
}

// ================= fp16 mma.sync GEMMs: 64x128 CTA tile, 8 warps (2m x 4n) =================
#define STR  72
#define STRT 136
#define PQ_SMEM_BYTES   ((64 + 128) * STR * 2)
#define UPD_SMEM_BYTES  (((64 + 128) * STR + 64 * STRT) * 2)

// ---- layer-0 PQ kernel: y=0 -> P = x@W1a^T + b1; y=1 -> Q = x@W1b^T (both fp16) ----
__global__ void __launch_bounds__(256, 3)
k_gemm_pq(const __half* __restrict__ A1,
          const __half* __restrict__ B1, const __half* __restrict__ B2,
          const float* __restrict__ bias,
          __half* __restrict__ Pf, __half* __restrict__ Ch, int M)
{
    extern __shared__ __half smh[];
    __half* As = smh;
    __half* Bs = smh + 64 * STR;

    const int tid = threadIdx.x;
    const int wid = tid >> 5, lane = tid & 31;
    const int g = lane >> 2, tig = lane & 3;
    const int warp_m = wid >> 2, warp_n = wid & 3;
    const int mw = warp_m * 32, nw = warp_n * 32;
    const int m0 = blockIdx.x * 64;
    const __half* B = (blockIdx.y == 0) ? B1 : B2;

    float acc[2][4][4];
    #pragma unroll
    for (int i = 0; i < 2; i++)
        #pragma unroll
        for (int j = 0; j < 4; j++)
            #pragma unroll
            for (int r = 0; r < 4; r++) acc[i][j][r] = 0.0f;

    for (int c = 0; c < 2; c++) {
        __syncthreads();
        #pragma unroll
        for (int u = 0; u < 2; u++) {
            int linear = u * 256 + tid;
            int row = linear >> 3, q = linear & 7;
            uint4 av = make_uint4(0u, 0u, 0u, 0u);
            if (m0 + row < M)
                av = *(const uint4*)&A1[(size_t)(m0 + row) * 128 + c * 64 + q * 8];
            *(uint4*)&As[row * STR + q * 8] = av;
        }
        #pragma unroll
        for (int u = 0; u < 4; u++) {
            int linear = u * 256 + tid;
            int row = linear >> 3, q = linear & 7;
            *(uint4*)&Bs[row * STR + q * 8] =
                *(const uint4*)&B[(size_t)row * 128 + c * 64 + q * 8];
        }
        __syncthreads();
        #pragma unroll
        for (int ks = 0; ks < 4; ks++) {
            const int k0 = ks * 16;
            uint32_t af[2][4], bf[4][2];
            #pragma unroll
            for (int i = 0; i < 2; i++) {
                const __half* r0 = &As[(mw + i * 16 + g) * STR + k0 + 2 * tig];
                const __half* r1 = r0 + 8 * STR;
                af[i][0] = *(const uint32_t*)r0;
                af[i][1] = *(const uint32_t*)r1;
                af[i][2] = *(const uint32_t*)(r0 + 8);
                af[i][3] = *(const uint32_t*)(r1 + 8);
            }
            #pragma unroll
            for (int j = 0; j < 4; j++) {
                const __half* rb = &Bs[(nw + j * 8 + g) * STR + k0 + 2 * tig];
                bf[j][0] = *(const uint32_t*)rb;
                bf[j][1] = *(const uint32_t*)(rb + 8);
            }
            #pragma unroll
            for (int i = 0; i < 2; i++)
                #pragma unroll
                for (int j = 0; j < 4; j++)
                    mma16(acc[i][j], af[i], bf[j]);
        }
    }

    float bcol[4][2];
    #pragma unroll
    for (int j = 0; j < 4; j++) {
        int col = nw + j * 8 + 2 * tig;
        bool haveb = (blockIdx.y == 0);
        bcol[j][0] = haveb ? bias[col]     : 0.0f;
        bcol[j][1] = haveb ? bias[col + 1] : 0.0f;
    }
    #pragma unroll
    for (int i = 0; i < 2; i++) {
        #pragma unroll
        for (int h = 0; h < 2; h++) {
            int row = m0 + mw + i * 16 + g + 8 * h;
            if (row >= M) continue;
            #pragma unroll
            for (int j = 0; j < 4; j++) {
                int col = nw + j * 8 + 2 * tig;
                float v0 = acc[i][j][2 * h] + bcol[j][0];
                float v1 = acc[i][j][2 * h + 1] + bcol[j][1];
                __half2 hv = __floats2half2_rn(v0, v1);
                if (blockIdx.y == 0) *(__half2*)&Pf[(size_t)row * 128 + col] = hv;
                else                 *(__half2*)&Ch[(size_t)row * 128 + col] = hv;
            }
        }
    }
}

// ---- fused UPD + LN (+ next-layer PQ, or readout mean) ----
template<int TAIL>
__global__ void __launch_bounds__(256, 3)
k_updln(const __half* __restrict__ A1, const __half* __restrict__ A2,
        const __half* __restrict__ B1, const __half* __restrict__ B2,
        const __half* __restrict__ B3,
        const __half* __restrict__ B4, const __half* __restrict__ B5,
        const float* __restrict__ bias, const float* __restrict__ bias2,
        const float* __restrict__ rowgate,
        const float* __restrict__ biasln,
        const float* __restrict__ lng, const float* __restrict__ lnb,
        const float* __restrict__ bP,
        __half* __restrict__ Ch, __half* __restrict__ Pf, __half* __restrict__ Qh, int M)
{
    extern __shared__ __half smh[];
    __half* As = smh;                        // [64][72]
    __half* Bs = smh + 64 * STR;             // [128][72]
    __half* T  = smh + (64 + 128) * STR;     // [64][136]

    const int tid = threadIdx.x;
    const int wid = tid >> 5, lane = tid & 31;
    const int g = lane >> 2, tig = lane & 3;
    const int warp_m = wid >> 2, warp_n = wid & 3;
    const int mw = warp_m * 32, nw = warp_n * 32;
    const int m0 = blockIdx.x * 64;

    float acc[2][4][4];
    #pragma unroll
    for (int i = 0; i < 2; i++)
        #pragma unroll
        for (int j = 0; j < 4; j++)
            #pragma unroll
            for (int r = 0; r < 4; r++) acc[i][j][r] = 0.0f;

    // ---- phase 1: dual-input GEMM ----
    for (int p = 0; p < 2; p++) {
        const __half* A = p ? A2 : A1;
        const __half* B = p ? B2 : B1;
        for (int c = 0; c < 2; c++) {
            __syncthreads();
            #pragma unroll
            for (int u = 0; u < 2; u++) {
                int linear = u * 256 + tid;
                int row = linear >> 3, q = linear & 7;
                uint4 av = make_uint4(0u, 0u, 0u, 0u);
                if (m0 + row < M)
                    av = *(const uint4*)&A[(size_t)(m0 + row) * 128 + c * 64 + q * 8];
                *(uint4*)&As[row * STR + q * 8] = av;
            }
            #pragma unroll
            for (int u = 0; u < 4; u++) {
                int linear = u * 256 + tid;
                int row = linear >> 3, q = linear & 7;
                *(uint4*)&Bs[row * STR + q * 8] =
                    *(const uint4*)&B[(size_t)row * 128 + c * 64 + q * 8];
            }
            __syncthreads();
            #pragma unroll
            for (int ks = 0; ks < 4; ks++) {
                const int k0 = ks * 16;
                uint32_t af[2][4], bf[4][2];
                #pragma unroll
                for (int i = 0; i < 2; i++) {
                    const __half* r0 = &As[(mw + i * 16 + g) * STR + k0 + 2 * tig];
                    const __half* r1 = r0 + 8 * STR;
                    af[i][0] = *(const uint32_t*)r0;
                    af[i][1] = *(const uint32_t*)r1;
                    af[i][2] = *(const uint32_t*)(r0 + 8);
                    af[i][3] = *(const uint32_t*)(r1 + 8);
                }
                #pragma unroll
                for (int j = 0; j < 4; j++) {
                    const __half* rb = &Bs[(nw + j * 8 + g) * STR + k0 + 2 * tig];
                    bf[j][0] = *(const uint32_t*)rb;
                    bf[j][1] = *(const uint32_t*)(rb + 8);
                }
                #pragma unroll
                for (int i = 0; i < 2; i++)
                    #pragma unroll
                    for (int j = 0; j < 4; j++)
                        mma16(acc[i][j], af[i], bf[j]);
            }
        }
    }

    // ---- epilogue 1: t -> smem T ----
    {
        float bcol[4][2], b2col[4][2];
        #pragma unroll
        for (int j = 0; j < 4; j++) {
            int col = nw + j * 8 + 2 * tig;
            bcol[j][0]  = bias[col];      bcol[j][1]  = bias[col + 1];
            b2col[j][0] = bias2[col];     b2col[j][1] = bias2[col + 1];
        }
        #pragma unroll
        for (int i = 0; i < 2; i++) {
            #pragma unroll
            for (int h = 0; h < 2; h++) {
                int rl = mw + i * 16 + g + 8 * h;
                int row = m0 + rl;
                float gt = (row < M) ? rowgate[row] : 0.f;
                #pragma unroll
                for (int j = 0; j < 4; j++) {
                    int col = nw + j * 8 + 2 * tig;
                    float v0 = fmaxf(acc[i][j][2*h]   + bcol[j][0] + gt * b2col[j][0], 0.f);
                    float v1 = fmaxf(acc[i][j][2*h+1] + bcol[j][1] + gt * b2col[j][1], 0.f);
                    *(__half2*)&T[rl * STRT + col] = __floats2half2_rn(v0, v1);
                }
            }
        }
    }
    #pragma unroll
    for (int i = 0; i < 2; i++)
        #pragma unroll
        for (int j = 0; j < 4; j++)
            #pragma unroll
            for (int r = 0; r < 4; r++) acc[i][j][r] = 0.0f;

    // ---- phase 2: t @ U2^T (A from smem T) ----
    for (int c = 0; c < 2; c++) {
        __syncthreads();
        #pragma unroll
        for (int u = 0; u < 4; u++) {
            int linear = u * 256 + tid;
            int row = linear >> 3, q = linear & 7;
            *(uint4*)&Bs[row * STR + q * 8] =
                *(const uint4*)&B3[(size_t)row * 128 + c * 64 + q * 8];
        }
        __syncthreads();
        #pragma unroll
        for (int ks = 0; ks < 4; ks++) {
            const int k0 = c * 64 + ks * 16;
            uint32_t af[2][4], bf[4][2];
            #pragma unroll
            for (int i = 0; i < 2; i++) {
                const __half* r0 = &T[(mw + i * 16 + g) * STRT + k0 + 2 * tig];
                const __half* r1 = r0 + 8 * STRT;
                af[i][0] = *(const uint32_t*)r0;
                af[i][1] = *(const uint32_t*)r1;
                af[i][2] = *(const uint32_t*)(r0 + 8);
                af[i][3] = *(const uint32_t*)(r1 + 8);
            }
            #pragma unroll
            for (int j = 0; j < 4; j++) {
                const __half* rb = &Bs[(nw + j * 8 + g) * STR + (ks * 16) + 2 * tig];
                bf[j][0] = *(const uint32_t*)rb;
                bf[j][1] = *(const uint32_t*)(rb + 8);
            }
            #pragma unroll
            for (int i = 0; i < 2; i++)
                #pragma unroll
                for (int j = 0; j < 4; j++)
                    mma16(acc[i][j], af[i], bf[j]);
        }
    }

    // ---- LN epilogue ----
    float csum[4][2];
    #pragma unroll
    for (int j = 0; j < 4; j++) { csum[j][0] = 0.f; csum[j][1] = 0.f; }
    {
        __syncthreads();
        float* sS  = (float*)As;
        float* sS2 = (float*)As + 256;
        float bcol[4][2], gcol[4][2], lcol[4][2];
        #pragma unroll
        for (int j = 0; j < 4; j++) {
            int col = nw + j * 8 + 2 * tig;
            bcol[j][0] = biasln[col];  bcol[j][1] = biasln[col + 1];
            gcol[j][0] = lng[col];     gcol[j][1] = lng[col + 1];
            lcol[j][0] = lnb[col];     lcol[j][1] = lnb[col + 1];
        }
        #pragma unroll
        for (int i = 0; i < 2; i++) {
            #pragma unroll
            for (int h = 0; h < 2; h++) {
                float s = 0.f, s2 = 0.f;
                #pragma unroll
                for (int j = 0; j < 4; j++) {
                    #pragma unroll
                    for (int r = 0; r < 2; r++) {
                        float v = acc[i][j][2 * h + r] + bcol[j][r];
                        s += v; s2 += v * v;
                    }
                }
                s  += __shfl_xor_sync(0xffffffffu, s, 1);
                s  += __shfl_xor_sync(0xffffffffu, s, 2);
                s2 += __shfl_xor_sync(0xffffffffu, s2, 1);
                s2 += __shfl_xor_sync(0xffffffffu, s2, 2);
                if (tig == 0) {
                    int rl = mw + i * 16 + g + 8 * h;
                    sS [rl * 4 + warp_n] = s;
                    sS2[rl * 4 + warp_n] = s2;
                }
            }
        }
        __syncthreads();
        #pragma unroll
        for (int i = 0; i < 2; i++) {
            #pragma unroll
            for (int h = 0; h < 2; h++) {
                int rl = mw + i * 16 + g + 8 * h;
                int row = m0 + rl;
                float s  = sS [rl * 4] + sS [rl * 4 + 1] + sS [rl * 4 + 2] + sS [rl * 4 + 3];
                float s2 = sS2[rl * 4] + sS2[rl * 4 + 1] + sS2[rl * 4 + 2] + sS2[rl * 4 + 3];
                float mu   = s * (1.0f / 128.0f);
                float var  = s2 * (1.0f / 128.0f) - mu * mu;
                float rstd = rsqrtf(var + 1e-5f);
                #pragma unroll
                for (int j = 0; j < 4; j++) {
                    int col = nw + j * 8 + 2 * tig;
                    float v0 = fmaxf((acc[i][j][2*h]   + bcol[j][0] - mu) * rstd * gcol[j][0] + lcol[j][0], 0.f);
                    float v1 = fmaxf((acc[i][j][2*h+1] + bcol[j][1] - mu) * rstd * gcol[j][1] + lcol[j][1], 0.f);
                    __half2 hv = __floats2half2_rn(v0, v1);
                    if constexpr (TAIL == 1) *(__half2*)&T[rl * STRT + col] = hv;
                    if (row < M) {
                        if constexpr (TAIL != 2) *(__half2*)&Ch[(size_t)row * 128 + col] = hv;
                        if constexpr (TAIL == 2) { csum[j][0] += v0; csum[j][1] += v1; }
                    }
                }
            }
        }
    }

    if constexpr (TAIL == 2) {
        __syncthreads();
        float* sgv = (float*)Bs;
        if (tid < 128) sgv[tid] = 0.f;
        __syncthreads();
        #pragma unroll
        for (int j = 0; j < 4; j++) {
            int col = nw + j * 8 + 2 * tig;
            atomicAdd(&sgv[col],     csum[j][0]);
            atomicAdd(&sgv[col + 1], csum[j][1]);
        }
        __syncthreads();
        if (tid < 128) atomicAdd(&g_gvec[tid], sgv[tid]);
    }

    if constexpr (TAIL == 1) {
        __syncthreads();
        #pragma unroll
        for (int pq = 0; pq < 2; pq++) {
            const __half* B = pq ? B5 : B4;
            #pragma unroll
            for (int i = 0; i < 2; i++)
                #pragma unroll
                for (int j = 0; j < 4; j++)
                    #pragma unroll
                    for (int r = 0; r < 4; r++) acc[i][j][r] = 0.0f;
            for (int c = 0; c < 2; c++) {
                __syncthreads();
                #pragma unroll
                for (int u = 0; u < 4; u++) {
                    int linear = u * 256 + tid;
                    int row = linear >> 3, q = linear & 7;
                    *(uint4*)&Bs[row * STR + q * 8] =
                        *(const uint4*)&B[(size_t)row * 128 + c * 64 + q * 8];
                }
                __syncthreads();
                #pragma unroll
                for (int ks = 0; ks < 4; ks++) {
                    const int k0 = c * 64 + ks * 16;
                    uint32_t af[2][4], bf[4][2];
                    #pragma unroll
                    for (int i = 0; i < 2; i++) {
                        const __half* r0 = &T[(mw + i * 16 + g) * STRT + k0 + 2 * tig];
                        const __half* r1 = r0 + 8 * STRT;
                        af[i][0] = *(const uint32_t*)r0;
                        af[i][1] = *(const uint32_t*)r1;
                        af[i][2] = *(const uint32_t*)(r0 + 8);
                        af[i][3] = *(const uint32_t*)(r1 + 8);
                    }
                    #pragma unroll
                    for (int j = 0; j < 4; j++) {
                        const __half* rb = &Bs[(nw + j * 8 + g) * STR + (ks * 16) + 2 * tig];
                        bf[j][0] = *(const uint32_t*)rb;
                        bf[j][1] = *(const uint32_t*)(rb + 8);
                    }
                    #pragma unroll
                    for (int i = 0; i < 2; i++)
                        #pragma unroll
                        for (int j = 0; j < 4; j++)
                            mma16(acc[i][j], af[i], bf[j]);
                }
            }
            if (pq == 0) {
                float bq[4][2];
                #pragma unroll
                for (int j = 0; j < 4; j++) {
                    int col = nw + j * 8 + 2 * tig;
                    bq[j][0] = bP[col]; bq[j][1] = bP[col + 1];
                }
                #pragma unroll
                for (int i = 0; i < 2; i++) {
                    #pragma unroll
                    for (int h = 0; h < 2; h++) {
                        int row = m0 + mw + i * 16 + g + 8 * h;
                        if (row >= M) continue;
                        #pragma unroll
                        for (int j = 0; j < 4; j++) {
                            int col = nw + j * 8 + 2 * tig;
                            *(__half2*)&Pf[(size_t)row * 128 + col] = __floats2half2_rn(
                                acc[i][j][2 * h] + bq[j][0], acc[i][j][2 * h + 1] + bq[j][1]);
                        }
                    }
                }
            } else {
                #pragma unroll
                for (int i = 0; i < 2; i++) {
                    #pragma unroll
                    for (int h = 0; h < 2; h++) {
                        int row = m0 + mw + i * 16 + g + 8 * h;
                        if (row >= M) continue;
                        #pragma unroll
                        for (int j = 0; j < 4; j++) {
                            int col = nw + j * 8 + 2 * tig;
                            *(__half2*)&Qh[(size_t)row * 128 + col] =
                                __floats2half2_rn(acc[i][j][2 * h], acc[i][j][2 * h + 1]);
                        }
                    }
                }
            }
        }
    }
}

// ================= edge aggregation: warp per node, fp16 P + Q, 4x unroll =================
__global__ void __launch_bounds__(256) k_aggr(const float* __restrict__ w1c, int N) {
    int warp = (blockIdx.x * blockDim.x + threadIdx.x) >> 5;
    int lane = threadIdx.x & 31;
    if (warp >= N) return;
    int node = warp;
    float4 p;
    {
        uint2 praw = *(const uint2*)&g_ph[(size_t)node * 128 + lane * 4];
        float2 p0 = __half22float2(*(const __half2*)&praw.x);
        float2 p1 = __half22float2(*(const __half2*)&praw.y);
        p.x = p0.x; p.y = p0.y; p.z = p1.x; p.w = p1.y;
    }
    float4 w = *(const float4*)&w1c[lane * 4];
    float4 acc = make_float4(0.f, 0.f, 0.f, 0.f);
    int s0 = g_rowptr[node], s1 = g_rowptr[node + 1];
    const int2* ep = g_edge;
    int j = s0;
    for (; j + 3 < s1; j += 4) {
        int2 e0 = __ldg(&ep[j]);
        int2 e1 = __ldg(&ep[j + 1]);
        int2 e2 = __ldg(&ep[j + 2]);
        int2 e3 = __ldg(&ep[j + 3]);
        uint2 r0 = *(const uint2*)&g_qh[(size_t)e0.x * 128 + lane * 4];
        uint2 r1 = *(const uint2*)&g_qh[(size_t)e1.x * 128 + lane * 4];
        uint2 r2 = *(const uint2*)&g_qh[(size_t)e2.x * 128 + lane * 4];
        uint2 r3 = *(const uint2*)&g_qh[(size_t)e3.x * 128 + lane * 4];
        float ea0 = __int_as_float(e0.y), ea1 = __int_as_float(e1.y);
        float ea2 = __int_as_float(e2.y), ea3 = __int_as_float(e3.y);
        float2 a0 = __half22float2(*(const __half2*)&r0.x);
        float2 a1 = __half22float2(*(const __half2*)&r0.y);
        float2 b0 = __half22float2(*(const __half2*)&r1.x);
        float2 b1 = __half22float2(*(const __half2*)&r1.y);
        float2 c0 = __half22float2(*(const __half2*)&r2.x);
        float2 c1 = __half22float2(*(const __half2*)&r2.y);
        float2 d0 = __half22float2(*(const __half2*)&r3.x);
        float2 d1 = __half22float2(*(const __half2*)&r3.y);
        acc.x += fmaxf(fmaf(ea0, w.x, p.x + a0.x), 0.f) + fmaxf(fmaf(ea1, w.x, p.x + b0.x), 0.f)
               + fmaxf(fmaf(ea2, w.x, p.x + c0.x), 0.f) + fmaxf(fmaf(ea3, w.x, p.x + d0.x), 0.f);
        acc.y += fmaxf(fmaf(ea0, w.y, p.y + a0.y), 0.f) + fmaxf(fmaf(ea1, w.y, p.y + b0.y), 0.f)
               + fmaxf(fmaf(ea2, w.y, p.y + c0.y), 0.f) + fmaxf(fmaf(ea3, w.y, p.y + d0.y), 0.f);
        acc.z += fmaxf(fmaf(ea0, w.z, p.z + a1.x), 0.f) + fmaxf(fmaf(ea1, w.z, p.z + b1.x), 0.f)
               + fmaxf(fmaf(ea2, w.z, p.z + c1.x), 0.f) + fmaxf(fmaf(ea3, w.z, p.z + d1.x), 0.f);
        acc.w += fmaxf(fmaf(ea0, w.w, p.w + a1.y), 0.f) + fmaxf(fmaf(ea1, w.w, p.w + b1.y), 0.f)
               + fmaxf(fmaf(ea2, w.w, p.w + c1.y), 0.f) + fmaxf(fmaf(ea3, w.w, p.w + d1.y), 0.f);
    }
    for (; j < s1; j++) {
        int2 e = __ldg(&ep[j]);
        float ea = __int_as_float(e.y);
        uint2 ra = *(const uint2*)&g_qh[(size_t)e.x * 128 + lane * 4];
        float2 a0 = __half22float2(*(const __half2*)&ra.x);
        float2 a1 = __half22float2(*(const __half2*)&ra.y);
        acc.x += fmaxf(fmaf(ea, w.x, p.x + a0.x), 0.f);
        acc.y += fmaxf(fmaf(ea, w.y, p.y + a0.y), 0.f);
        acc.z += fmaxf(fmaf(ea, w.z, p.z + a1.x), 0.f);
        acc.w += fmaxf(fmaf(ea, w.w, p.w + a1.y), 0.f);
    }
    float inv = g_invdeg[node];
    __half2 h0 = __floats2half2_rn(acc.x * inv, acc.y * inv);
    __half2 h1 = __floats2half2_rn(acc.z * inv, acc.w * inv);
    uint2 u; u.x = *(uint32_t*)&h0; u.y = *(uint32_t*)&h1;
    *(uint2*)&g_Hh[(size_t)node * 128 + lane * 4] = u;
}

// ================= readout =================
__global__ void k_out(const float* __restrict__ W1, const float* __restrict__ b1,
                      const float* __restrict__ W2, const float* __restrict__ b2,
                      float* __restrict__ out, float invN) {
    __shared__ float gs[128];
    __shared__ float hs[128];
    int c = threadIdx.x;
    gs[c] = g_gvec[c] * invN;
    __syncthreads();
    float a = b1[c];
    #pragma unroll 8
    for (int k = 0; k < 128; k++) a = fmaf(gs[k], W1[k * 128 + c], a);
    hs[c] = fmaxf(a, 0.0f);
    __syncthreads();
    float o = b2[c];
    #pragma unroll 8
    for (int k = 0; k < 128; k++) o = fmaf(hs[k], W2[k * 128 + c], o);
    out[c] = o;
}

// ================= launch =================
extern "C" void kernel_launch(void* const* d_in, const int* in_sizes, int n_in,
                              void* d_out, int out_size) {
    const float* node_feat = (const float*)d_in[0];
    const float* edge_attr = (const float*)d_in[1];
    const float* enc_W  = (const float*)d_in[2];
    const float* enc_b  = (const float*)d_in[3];
    const float* mlp_W1 = (const float*)d_in[4];
    const float* mlp_b1 = (const float*)d_in[5];
    const float* mlp_W2 = (const float*)d_in[6];
    const float* mlp_b2 = (const float*)d_in[7];
    const float* upd_W1 = (const float*)d_in[8];
    const float* upd_b1 = (const float*)d_in[9];
    const float* upd_W2 = (const float*)d_in[10];
    const float* upd_b2 = (const float*)d_in[11];
    const float* ln_g   = (const float*)d_in[12];
    const float* ln_b   = (const float*)d_in[13];
    const float* out_W1 = (const float*)d_in[14];
    const float* out_b1 = (const float*)d_in[15];
    const float* out_W2 = (const float*)d_in[16];
    const float* out_b2 = (const float*)d_in[17];
    const int*   ei     = (const int*)d_in[18];

    const int N = NODES;
    const int E = EDGES;

    float *pbc, *pgate;
    __half *pxh, *pph, *pqh, *pHh, *pwTh;
    cudaGetSymbolAddress((void**)&pxh,   g_xh);
    cudaGetSymbolAddress((void**)&pph,   g_ph);
    cudaGetSymbolAddress((void**)&pqh,   g_qh);
    cudaGetSymbolAddress((void**)&pHh,   g_Hh);
    cudaGetSymbolAddress((void**)&pwTh,  g_wTh);
    cudaGetSymbolAddress((void**)&pbc,   g_bc);
    cudaGetSymbolAddress((void**)&pgate, g_gate);

    cudaFuncSetAttribute(k_gemm_pq, cudaFuncAttributeMaxDynamicSharedMemorySize, PQ_SMEM_BYTES);
    cudaFuncSetAttribute(k_updln<1>, cudaFuncAttributeMaxDynamicSharedMemorySize, UPD_SMEM_BYTES);
    cudaFuncSetAttribute(k_updln<2>, cudaFuncAttributeMaxDynamicSharedMemorySize, UPD_SMEM_BYTES);

    // CSR build
    k_init<<<(N + 255) / 256, 256>>>(ei, N);
    k_count<<<(E + 255) / 256, 256>>>(ei, E);
    k_scan1<<<(N + 1023) / 1024, 1024>>>(N);
    k_scan3<<<(N + 255) / 256, 256>>>(N);
    k_scatter<<<(E + 255) / 256, 256>>>(ei, edge_attr, E);

    // encoder + weight prep
    k_encode<<<(N * HID + 255) / 256, 256>>>(node_feat, enc_W, enc_b, N);
    k_repackT<<<NLAYER * 4 * 16384 / 256, 256>>>(mlp_W1, upd_W1, upd_W2);
    k_fuseW<<<dim3(128, NLAYER), 128>>>(mlp_W2, upd_W1, mlp_b2);

    const int gt64 = (N + 63) / 64;

    // layer 0 PQ (from encoder x)
    k_gemm_pq<<<dim3(gt64, 2), 256, PQ_SMEM_BYTES>>>(
        pxh, pwTh + 0 * 16384, pwTh + 1 * 16384, mlp_b1, pph, pqh, N);

    for (int l = 0; l < NLAYER; l++) {
        const float* W1l = mlp_W1 + (size_t)l * 257 * 128;
        __half* wl = pwTh + (size_t)l * 5 * 16384;

        k_aggr<<<(N + 7) / 8, 256>>>(W1l + 256 * 128, N);

        if (l < NLAYER - 1) {
            __half* wn = pwTh + (size_t)(l + 1) * 5 * 16384;
            k_updln<1><<<gt64, 256, UPD_SMEM_BYTES>>>(
                pxh, pHh, wl + 2 * 16384, wl + 4 * 16384, wl + 3 * 16384,
                wn + 0 * 16384, wn + 1 * 16384,
                upd_b1 + l * 128, pbc + l * 128, pgate,
                upd_b2 + l * 128, ln_g + l * 128, ln_b + l * 128,
                mlp_b1 + (l + 1) * 128,
                pxh, pph, pqh, N);
        } else {
            k_updln<2><<<gt64, 256, UPD_SMEM_BYTES>>>(
                pxh, pHh, wl + 2 * 16384, wl + 4 * 16384, wl + 3 * 16384,
                nullptr, nullptr,
                upd_b1 + l * 128, pbc + l * 128, pgate,
                upd_b2 + l * 128, ln_g + l * 128, ln_b + l * 128,
                nullptr,
                pxh, pph, pqh, N);
        }
    }

    k_out<<<1, 128>>>(out_W1, out_b1, out_W2, out_b2, (float*)d_out, 1.0f / (float)N);
}

// round 12
// speedup vs baseline: 1.2311x; 1.0661x over previous
#include <cuda_runtime.h>
#include <cuda_fp16.h>
#include <cstdint>

#define NODES 50000
#define EDGES 800000
#define HID   128
#define NLAYER 3

// ---------------- scratch (static device globals; no allocation) ----------------
__device__ __half g_xh [NODES * HID];      // node state, fp16
__device__ __half g_ph [NODES * HID];      // P per node (fp16, b1 folded in)
__device__ __half g_qh [NODES * HID];      // Q per node (fp16, gathered per edge)
__device__ __half g_Hh [NODES * HID];      // inv_deg * segment_sum(relu_h), fp16
__device__ uint32_t g_edge[EDGES];         // src (lo 16) | ea fp16 bits (hi 16)
__device__ int   g_deg [NODES];
__device__ int   g_tmp [NODES];
__device__ int   g_rowptr[NODES + 1];
__device__ int   g_cursor[NODES];
__device__ float g_invdeg[NODES];
__device__ float g_gate  [NODES];
__device__ __half g_wTh[NLAYER * 5 * HID * HID];  // B^T fp16: 0=W1a 1=W1b 2=U1a 3=U2 4=Wc
__device__ float g_bc  [NLAYER * HID];            // b2 @ U1b per layer
__device__ float g_gvec[HID];
__device__ int   g_is64;
__device__ int   g_bsum[64];

// ================= helpers =================
__device__ __forceinline__ void mma16(float* c, const uint32_t* a, const uint32_t* b) {
    asm volatile(
        "mma.sync.aligned.m16n8k16.row.col.f32.f16.f16.f32 "
        "{%0,%1,%2,%3},{%4,%5,%6,%7},{%8,%9},{%0,%1,%2,%3};"
        : "+f"(c[0]), "+f"(c[1]), "+f"(c[2]), "+f"(c[3])
        : "r"(a[0]), "r"(a[1]), "r"(a[2]), "r"(a[3]), "r"(b[0]), "r"(b[1]));
}

// ================= CSR build =================
__global__ void k_init(const int* __restrict__ ei, int N) {
    int i = blockIdx.x * blockDim.x + threadIdx.x;
    if (i < N) g_deg[i] = 0;
    if (i < 128) g_gvec[i] = 0.0f;
    if (i == 0) {
        int z = 1;
        #pragma unroll
        for (int k = 1; k < 16; k += 2) if (ei[k] != 0) z = 0;
        g_is64 = z;
    }
}
__global__ void k_count(const int* __restrict__ ei, int E) {
    int e = blockIdx.x * blockDim.x + threadIdx.x;
    if (e >= E) return;
    int is64 = g_is64;
    int dst = is64 ? ei[2 * E + 2 * e] : ei[E + e];
    atomicAdd(&g_deg[dst], 1);
}
__global__ void k_scan1(int N) {
    __shared__ int s[1024];
    int tid = threadIdx.x;
    int i = blockIdx.x * 1024 + tid;
    int v = (i < N) ? g_deg[i] : 0;
    s[tid] = v;
    __syncthreads();
    for (int off = 1; off < 1024; off <<= 1) {
        int t = (tid >= off) ? s[tid - off] : 0;
        __syncthreads();
        s[tid] += t;
        __syncthreads();
    }
    if (i < N) g_tmp[i] = s[tid];
    if (tid == 1023) g_bsum[blockIdx.x] = s[1023];
}
__global__ void k_scan3(int N) {
    __shared__ int sred[64];
    int tid = threadIdx.x;
    int blk = (blockIdx.x * 256) >> 10;
    if (tid < 64) sred[tid] = (tid < blk) ? g_bsum[tid] : 0;
    __syncthreads();
    #pragma unroll
    for (int off = 32; off > 0; off >>= 1) {
        if (tid < off) sred[tid] += sred[tid + off];
        __syncthreads();
    }
    int boff = sred[0];
    int i = blockIdx.x * 256 + tid;
    if (i >= N) return;
    int incl = g_tmp[i] + boff;
    int d = g_deg[i];
    int excl = incl - d;
    g_rowptr[i] = excl;
    g_cursor[i] = excl;
    g_invdeg[i] = 1.0f / fmaxf((float)d, 1.0f);
    g_gate[i]   = (d > 0) ? 1.0f : 0.0f;
    if (i == N - 1) g_rowptr[N] = incl;
}
__global__ void k_scatter(const int* __restrict__ ei, const float* __restrict__ ea, int E) {
    int e = blockIdx.x * blockDim.x + threadIdx.x;
    if (e >= E) return;
    int is64 = g_is64;
    int src = is64 ? ei[2 * e]         : ei[e];
    int dst = is64 ? ei[2 * E + 2 * e] : ei[E + e];
    int pos = atomicAdd(&g_cursor[dst], 1);
    uint32_t eabits = (uint32_t)__half_as_ushort(__float2half_rn(ea[e]));
    g_edge[pos] = (uint32_t)src | (eabits << 16);
}

// ================= encoder =================
__global__ void k_encode(const float* __restrict__ nf, const float* __restrict__ W,
                         const float* __restrict__ b, int N) {
    int t = blockIdx.x * blockDim.x + threadIdx.x;
    if (t >= N * HID) return;
    int n = t >> 7, c = t & 127;
    float acc = b[c];
    #pragma unroll
    for (int k = 0; k < 5; k++) acc = fmaf(nf[n * 5 + k], W[k * HID + c], acc);
    g_xh[t] = __float2half_rn(acc);
}

// ================= weight repack (ALL layers, transpose, to fp16) =================
__global__ void k_repackT(const float* __restrict__ mlp_W1, const float* __restrict__ upd_W1,
                          const float* __restrict__ upd_W2) {
    int t = blockIdx.x * blockDim.x + threadIdx.x;
    int l = t / (4 * 16384);
    int r = t % (4 * 16384);
    int w = r >> 14;
    int j = (r >> 7) & 127;
    int k = r & 127;
    const float* W1 = mlp_W1 + (size_t)l * 257 * 128;
    const float* U1 = upd_W1 + (size_t)l * 256 * 128;
    const float* U2 = upd_W2 + (size_t)l * 128 * 128;
    float v;
    switch (w) {
        case 0:  v = W1[k * 128 + j];          break;
        case 1:  v = W1[(128 + k) * 128 + j];  break;
        case 2:  v = U1[k * 128 + j];          break;
        default: v = U2[k * 128 + j];          break;
    }
    g_wTh[(size_t)l * 5 * 16384 + (size_t)w * 16384 + j * 128 + k] = __float2half_rn(v);
}

// ================= fused small weight: Wc = W2 @ U1b, bc = b2 @ U1b =================
__global__ void k_fuseW(const float* __restrict__ mlp_W2, const float* __restrict__ upd_W1,
                        const float* __restrict__ mlp_b2) {
    __shared__ float w2row[128];
    int k = blockIdx.x, l = blockIdx.y, j = threadIdx.x;
    const float* W2 = mlp_W2 + (size_t)l * 128 * 128;
    const float* U1 = upd_W1 + (size_t)l * 256 * 128;
    const float* b2 = mlp_b2 + l * 128;
    w2row[j] = W2[k * 128 + j];
    __syncthreads();
    float acc = 0.f;
    #pragma unroll 8
    for (int t = 0; t < 128; t++) acc = fmaf(w2row[t], U1[(128 + t) * 128 + j], acc);
    g_wTh[(size_t)l * 5 * 16384 + 4 * 16384 + j * 128 + k] = __float2half_rn(acc);
    if (k == 0) {
        float bacc = 0.f;
        #pragma unroll 8
        for (int t = 0; t < 128; t++) bacc = fmaf(b2[t], U1[(128 + t) * 128 + j], bacc);
        g_bc[l * 128 + j] = bacc;
    }
}

// ================= fp16 mma.sync GEMMs: 64x128 CTA tile, 8 warps (2m x 4n) =================
#define STR  72
#define STRT 136
#define PQ_SMEM_BYTES   ((64 + 128) * STR * 2)
#define UPD_SMEM_BYTES  (((64 + 128) * STR + 64 * STRT) * 2)

// ---- layer-0 PQ kernel: y=0 -> P = x@W1a^T + b1; y=1 -> Q = x@W1b^T (both fp16) ----
__global__ void __launch_bounds__(256, 3)
k_gemm_pq(const __half* __restrict__ A1,
          const __half* __restrict__ B1, const __half* __restrict__ B2,
          const float* __restrict__ bias,
          __half* __restrict__ Pf, __half* __restrict__ Ch, int M)
{
    extern __shared__ __half smh[];
    __half* As = smh;
    __half* Bs = smh + 64 * STR;

    const int tid = threadIdx.x;
    const int wid = tid >> 5, lane = tid & 31;
    const int g = lane >> 2, tig = lane & 3;
    const int warp_m = wid >> 2, warp_n = wid & 3;
    const int mw = warp_m * 32, nw = warp_n * 32;
    const int m0 = blockIdx.x * 64;
    const __half* B = (blockIdx.y == 0) ? B1 : B2;

    float acc[2][4][4];
    #pragma unroll
    for (int i = 0; i < 2; i++)
        #pragma unroll
        for (int j = 0; j < 4; j++)
            #pragma unroll
            for (int r = 0; r < 4; r++) acc[i][j][r] = 0.0f;

    for (int c = 0; c < 2; c++) {
        __syncthreads();
        #pragma unroll
        for (int u = 0; u < 2; u++) {
            int linear = u * 256 + tid;
            int row = linear >> 3, q = linear & 7;
            uint4 av = make_uint4(0u, 0u, 0u, 0u);
            if (m0 + row < M)
                av = *(const uint4*)&A1[(size_t)(m0 + row) * 128 + c * 64 + q * 8];
            *(uint4*)&As[row * STR + q * 8] = av;
        }
        #pragma unroll
        for (int u = 0; u < 4; u++) {
            int linear = u * 256 + tid;
            int row = linear >> 3, q = linear & 7;
            *(uint4*)&Bs[row * STR + q * 8] =
                *(const uint4*)&B[(size_t)row * 128 + c * 64 + q * 8];
        }
        __syncthreads();
        #pragma unroll
        for (int ks = 0; ks < 4; ks++) {
            const int k0 = ks * 16;
            uint32_t af[2][4], bf[4][2];
            #pragma unroll
            for (int i = 0; i < 2; i++) {
                const __half* r0 = &As[(mw + i * 16 + g) * STR + k0 + 2 * tig];
                const __half* r1 = r0 + 8 * STR;
                af[i][0] = *(const uint32_t*)r0;
                af[i][1] = *(const uint32_t*)r1;
                af[i][2] = *(const uint32_t*)(r0 + 8);
                af[i][3] = *(const uint32_t*)(r1 + 8);
            }
            #pragma unroll
            for (int j = 0; j < 4; j++) {
                const __half* rb = &Bs[(nw + j * 8 + g) * STR + k0 + 2 * tig];
                bf[j][0] = *(const uint32_t*)rb;
                bf[j][1] = *(const uint32_t*)(rb + 8);
            }
            #pragma unroll
            for (int i = 0; i < 2; i++)
                #pragma unroll
                for (int j = 0; j < 4; j++)
                    mma16(acc[i][j], af[i], bf[j]);
        }
    }

    float bcol[4][2];
    #pragma unroll
    for (int j = 0; j < 4; j++) {
        int col = nw + j * 8 + 2 * tig;
        bool haveb = (blockIdx.y == 0);
        bcol[j][0] = haveb ? bias[col]     : 0.0f;
        bcol[j][1] = haveb ? bias[col + 1] : 0.0f;
    }
    #pragma unroll
    for (int i = 0; i < 2; i++) {
        #pragma unroll
        for (int h = 0; h < 2; h++) {
            int row = m0 + mw + i * 16 + g + 8 * h;
            if (row >= M) continue;
            #pragma unroll
            for (int j = 0; j < 4; j++) {
                int col = nw + j * 8 + 2 * tig;
                float v0 = acc[i][j][2 * h] + bcol[j][0];
                float v1 = acc[i][j][2 * h + 1] + bcol[j][1];
                __half2 hv = __floats2half2_rn(v0, v1);
                if (blockIdx.y == 0) *(__half2*)&Pf[(size_t)row * 128 + col] = hv;
                else                 *(__half2*)&Ch[(size_t)row * 128 + col] = hv;
            }
        }
    }
}

// ---- fused UPD + LN (+ next-layer PQ, or readout mean) ----
template<int TAIL>
__global__ void __launch_bounds__(256, 3)
k_updln(const __half* __restrict__ A1, const __half* __restrict__ A2,
        const __half* __restrict__ B1, const __half* __restrict__ B2,
        const __half* __restrict__ B3,
        const __half* __restrict__ B4, const __half* __restrict__ B5,
        const float* __restrict__ bias, const float* __restrict__ bias2,
        const float* __restrict__ rowgate,
        const float* __restrict__ biasln,
        const float* __restrict__ lng, const float* __restrict__ lnb,
        const float* __restrict__ bP,
        __half* __restrict__ Ch, __half* __restrict__ Pf, __half* __restrict__ Qh, int M)
{
    extern __shared__ __half smh[];
    __half* As = smh;                        // [64][72]
    __half* Bs = smh + 64 * STR;             // [128][72]
    __half* T  = smh + (64 + 128) * STR;     // [64][136]

    const int tid = threadIdx.x;
    const int wid = tid >> 5, lane = tid & 31;
    const int g = lane >> 2, tig = lane & 3;
    const int warp_m = wid >> 2, warp_n = wid & 3;
    const int mw = warp_m * 32, nw = warp_n * 32;
    const int m0 = blockIdx.x * 64;

    float acc[2][4][4];
    #pragma unroll
    for (int i = 0; i < 2; i++)
        #pragma unroll
        for (int j = 0; j < 4; j++)
            #pragma unroll
            for (int r = 0; r < 4; r++) acc[i][j][r] = 0.0f;

    // ---- phase 1: dual-input GEMM ----
    for (int p = 0; p < 2; p++) {
        const __half* A = p ? A2 : A1;
        const __half* B = p ? B2 : B1;
        for (int c = 0; c < 2; c++) {
            __syncthreads();
            #pragma unroll
            for (int u = 0; u < 2; u++) {
                int linear = u * 256 + tid;
                int row = linear >> 3, q = linear & 7;
                uint4 av = make_uint4(0u, 0u, 0u, 0u);
                if (m0 + row < M)
                    av = *(const uint4*)&A[(size_t)(m0 + row) * 128 + c * 64 + q * 8];
                *(uint4*)&As[row * STR + q * 8] = av;
            }
            #pragma unroll
            for (int u = 0; u < 4; u++) {
                int linear = u * 256 + tid;
                int row = linear >> 3, q = linear & 7;
                *(uint4*)&Bs[row * STR + q * 8] =
                    *(const uint4*)&B[(size_t)row * 128 + c * 64 + q * 8];
            }
            __syncthreads();
            #pragma unroll
            for (int ks = 0; ks < 4; ks++) {
                const int k0 = ks * 16;
                uint32_t af[2][4], bf[4][2];
                #pragma unroll
                for (int i = 0; i < 2; i++) {
                    const __half* r0 = &As[(mw + i * 16 + g) * STR + k0 + 2 * tig];
                    const __half* r1 = r0 + 8 * STR;
                    af[i][0] = *(const uint32_t*)r0;
                    af[i][1] = *(const uint32_t*)r1;
                    af[i][2] = *(const uint32_t*)(r0 + 8);
                    af[i][3] = *(const uint32_t*)(r1 + 8);
                }
                #pragma unroll
                for (int j = 0; j < 4; j++) {
                    const __half* rb = &Bs[(nw + j * 8 + g) * STR + k0 + 2 * tig];
                    bf[j][0] = *(const uint32_t*)rb;
                    bf[j][1] = *(const uint32_t*)(rb + 8);
                }
                #pragma unroll
                for (int i = 0; i < 2; i++)
                    #pragma unroll
                    for (int j = 0; j < 4; j++)
                        mma16(acc[i][j], af[i], bf[j]);
            }
        }
    }

    // ---- epilogue 1: t -> smem T ----
    {
        float bcol[4][2], b2col[4][2];
        #pragma unroll
        for (int j = 0; j < 4; j++) {
            int col = nw + j * 8 + 2 * tig;
            bcol[j][0]  = bias[col];      bcol[j][1]  = bias[col + 1];
            b2col[j][0] = bias2[col];     b2col[j][1] = bias2[col + 1];
        }
        #pragma unroll
        for (int i = 0; i < 2; i++) {
            #pragma unroll
            for (int h = 0; h < 2; h++) {
                int rl = mw + i * 16 + g + 8 * h;
                int row = m0 + rl;
                float gt = (row < M) ? rowgate[row] : 0.f;
                #pragma unroll
                for (int j = 0; j < 4; j++) {
                    int col = nw + j * 8 + 2 * tig;
                    float v0 = fmaxf(acc[i][j][2*h]   + bcol[j][0] + gt * b2col[j][0], 0.f);
                    float v1 = fmaxf(acc[i][j][2*h+1] + bcol[j][1] + gt * b2col[j][1], 0.f);
                    *(__half2*)&T[rl * STRT + col] = __floats2half2_rn(v0, v1);
                }
            }
        }
    }
    #pragma unroll
    for (int i = 0; i < 2; i++)
        #pragma unroll
        for (int j = 0; j < 4; j++)
            #pragma unroll
            for (int r = 0; r < 4; r++) acc[i][j][r] = 0.0f;

    // ---- phase 2: t @ U2^T (A from smem T) ----
    for (int c = 0; c < 2; c++) {
        __syncthreads();
        #pragma unroll
        for (int u = 0; u < 4; u++) {
            int linear = u * 256 + tid;
            int row = linear >> 3, q = linear & 7;
            *(uint4*)&Bs[row * STR + q * 8] =
                *(const uint4*)&B3[(size_t)row * 128 + c * 64 + q * 8];
        }
        __syncthreads();
        #pragma unroll
        for (int ks = 0; ks < 4; ks++) {
            const int k0 = c * 64 + ks * 16;
            uint32_t af[2][4], bf[4][2];
            #pragma unroll
            for (int i = 0; i < 2; i++) {
                const __half* r0 = &T[(mw + i * 16 + g) * STRT + k0 + 2 * tig];
                const __half* r1 = r0 + 8 * STRT;
                af[i][0] = *(const uint32_t*)r0;
                af[i][1] = *(const uint32_t*)r1;
                af[i][2] = *(const uint32_t*)(r0 + 8);
                af[i][3] = *(const uint32_t*)(r1 + 8);
            }
            #pragma unroll
            for (int j = 0; j < 4; j++) {
                const __half* rb = &Bs[(nw + j * 8 + g) * STR + (ks * 16) + 2 * tig];
                bf[j][0] = *(const uint32_t*)rb;
                bf[j][1] = *(const uint32_t*)(rb + 8);
            }
            #pragma unroll
            for (int i = 0; i < 2; i++)
                #pragma unroll
                for (int j = 0; j < 4; j++)
                    mma16(acc[i][j], af[i], bf[j]);
        }
    }

    // ---- LN epilogue ----
    float csum[4][2];
    #pragma unroll
    for (int j = 0; j < 4; j++) { csum[j][0] = 0.f; csum[j][1] = 0.f; }
    {
        __syncthreads();
        float* sS  = (float*)As;
        float* sS2 = (float*)As + 256;
        float bcol[4][2], gcol[4][2], lcol[4][2];
        #pragma unroll
        for (int j = 0; j < 4; j++) {
            int col = nw + j * 8 + 2 * tig;
            bcol[j][0] = biasln[col];  bcol[j][1] = biasln[col + 1];
            gcol[j][0] = lng[col];     gcol[j][1] = lng[col + 1];
            lcol[j][0] = lnb[col];     lcol[j][1] = lnb[col + 1];
        }
        #pragma unroll
        for (int i = 0; i < 2; i++) {
            #pragma unroll
            for (int h = 0; h < 2; h++) {
                float s = 0.f, s2 = 0.f;
                #pragma unroll
                for (int j = 0; j < 4; j++) {
                    #pragma unroll
                    for (int r = 0; r < 2; r++) {
                        float v = acc[i][j][2 * h + r] + bcol[j][r];
                        s += v; s2 += v * v;
                    }
                }
                s  += __shfl_xor_sync(0xffffffffu, s, 1);
                s  += __shfl_xor_sync(0xffffffffu, s, 2);
                s2 += __shfl_xor_sync(0xffffffffu, s2, 1);
                s2 += __shfl_xor_sync(0xffffffffu, s2, 2);
                if (tig == 0) {
                    int rl = mw + i * 16 + g + 8 * h;
                    sS [rl * 4 + warp_n] = s;
                    sS2[rl * 4 + warp_n] = s2;
                }
            }
        }
        __syncthreads();
        #pragma unroll
        for (int i = 0; i < 2; i++) {
            #pragma unroll
            for (int h = 0; h < 2; h++) {
                int rl = mw + i * 16 + g + 8 * h;
                int row = m0 + rl;
                float s  = sS [rl * 4] + sS [rl * 4 + 1] + sS [rl * 4 + 2] + sS [rl * 4 + 3];
                float s2 = sS2[rl * 4] + sS2[rl * 4 + 1] + sS2[rl * 4 + 2] + sS2[rl * 4 + 3];
                float mu   = s * (1.0f / 128.0f);
                float var  = s2 * (1.0f / 128.0f) - mu * mu;
                float rstd = rsqrtf(var + 1e-5f);
                #pragma unroll
                for (int j = 0; j < 4; j++) {
                    int col = nw + j * 8 + 2 * tig;
                    float v0 = fmaxf((acc[i][j][2*h]   + bcol[j][0] - mu) * rstd * gcol[j][0] + lcol[j][0], 0.f);
                    float v1 = fmaxf((acc[i][j][2*h+1] + bcol[j][1] - mu) * rstd * gcol[j][1] + lcol[j][1], 0.f);
                    __half2 hv = __floats2half2_rn(v0, v1);
                    if constexpr (TAIL == 1) *(__half2*)&T[rl * STRT + col] = hv;
                    if (row < M) {
                        if constexpr (TAIL != 2) *(__half2*)&Ch[(size_t)row * 128 + col] = hv;
                        if constexpr (TAIL == 2) { csum[j][0] += v0; csum[j][1] += v1; }
                    }
                }
            }
        }
    }

    if constexpr (TAIL == 2) {
        __syncthreads();
        float* sgv = (float*)Bs;
        if (tid < 128) sgv[tid] = 0.f;
        __syncthreads();
        #pragma unroll
        for (int j = 0; j < 4; j++) {
            int col = nw + j * 8 + 2 * tig;
            atomicAdd(&sgv[col],     csum[j][0]);
            atomicAdd(&sgv[col + 1], csum[j][1]);
        }
        __syncthreads();
        if (tid < 128) atomicAdd(&g_gvec[tid], sgv[tid]);
    }

    if constexpr (TAIL == 1) {
        __syncthreads();
        #pragma unroll
        for (int pq = 0; pq < 2; pq++) {
            const __half* B = pq ? B5 : B4;
            #pragma unroll
            for (int i = 0; i < 2; i++)
                #pragma unroll
                for (int j = 0; j < 4; j++)
                    #pragma unroll
                    for (int r = 0; r < 4; r++) acc[i][j][r] = 0.0f;
            for (int c = 0; c < 2; c++) {
                __syncthreads();
                #pragma unroll
                for (int u = 0; u < 4; u++) {
                    int linear = u * 256 + tid;
                    int row = linear >> 3, q = linear & 7;
                    *(uint4*)&Bs[row * STR + q * 8] =
                        *(const uint4*)&B[(size_t)row * 128 + c * 64 + q * 8];
                }
                __syncthreads();
                #pragma unroll
                for (int ks = 0; ks < 4; ks++) {
                    const int k0 = c * 64 + ks * 16;
                    uint32_t af[2][4], bf[4][2];
                    #pragma unroll
                    for (int i = 0; i < 2; i++) {
                        const __half* r0 = &T[(mw + i * 16 + g) * STRT + k0 + 2 * tig];
                        const __half* r1 = r0 + 8 * STRT;
                        af[i][0] = *(const uint32_t*)r0;
                        af[i][1] = *(const uint32_t*)r1;
                        af[i][2] = *(const uint32_t*)(r0 + 8);
                        af[i][3] = *(const uint32_t*)(r1 + 8);
                    }
                    #pragma unroll
                    for (int j = 0; j < 4; j++) {
                        const __half* rb = &Bs[(nw + j * 8 + g) * STR + (ks * 16) + 2 * tig];
                        bf[j][0] = *(const uint32_t*)rb;
                        bf[j][1] = *(const uint32_t*)(rb + 8);
                    }
                    #pragma unroll
                    for (int i = 0; i < 2; i++)
                        #pragma unroll
                        for (int j = 0; j < 4; j++)
                            mma16(acc[i][j], af[i], bf[j]);
                }
            }
            if (pq == 0) {
                float bq[4][2];
                #pragma unroll
                for (int j = 0; j < 4; j++) {
                    int col = nw + j * 8 + 2 * tig;
                    bq[j][0] = bP[col]; bq[j][1] = bP[col + 1];
                }
                #pragma unroll
                for (int i = 0; i < 2; i++) {
                    #pragma unroll
                    for (int h = 0; h < 2; h++) {
                        int row = m0 + mw + i * 16 + g + 8 * h;
                        if (row >= M) continue;
                        #pragma unroll
                        for (int j = 0; j < 4; j++) {
                            int col = nw + j * 8 + 2 * tig;
                            *(__half2*)&Pf[(size_t)row * 128 + col] = __floats2half2_rn(
                                acc[i][j][2 * h] + bq[j][0], acc[i][j][2 * h + 1] + bq[j][1]);
                        }
                    }
                }
            } else {
                #pragma unroll
                for (int i = 0; i < 2; i++) {
                    #pragma unroll
                    for (int h = 0; h < 2; h++) {
                        int row = m0 + mw + i * 16 + g + 8 * h;
                        if (row >= M) continue;
                        #pragma unroll
                        for (int j = 0; j < 4; j++) {
                            int col = nw + j * 8 + 2 * tig;
                            *(__half2*)&Qh[(size_t)row * 128 + col] =
                                __floats2half2_rn(acc[i][j][2 * h], acc[i][j][2 * h + 1]);
                        }
                    }
                }
            }
        }
    }
}

// ================= edge aggregation: warp per node, packed edges, 4x unroll =================
__global__ void __launch_bounds__(256) k_aggr(const float* __restrict__ w1c, int N) {
    int warp = (blockIdx.x * blockDim.x + threadIdx.x) >> 5;
    int lane = threadIdx.x & 31;
    if (warp >= N) return;
    int node = warp;
    float4 p;
    {
        uint2 praw = *(const uint2*)&g_ph[(size_t)node * 128 + lane * 4];
        float2 p0 = __half22float2(*(const __half2*)&praw.x);
        float2 p1 = __half22float2(*(const __half2*)&praw.y);
        p.x = p0.x; p.y = p0.y; p.z = p1.x; p.w = p1.y;
    }
    float4 w = *(const float4*)&w1c[lane * 4];
    float4 acc = make_float4(0.f, 0.f, 0.f, 0.f);
    int s0 = g_rowptr[node], s1 = g_rowptr[node + 1];
    const uint32_t* ep = g_edge;
    int j = s0;
    for (; j + 3 < s1; j += 4) {
        uint32_t e0 = __ldg(&ep[j]);
        uint32_t e1 = __ldg(&ep[j + 1]);
        uint32_t e2 = __ldg(&ep[j + 2]);
        uint32_t e3 = __ldg(&ep[j + 3]);
        uint2 r0 = *(const uint2*)&g_qh[(size_t)(e0 & 0xFFFFu) * 128 + lane * 4];
        uint2 r1 = *(const uint2*)&g_qh[(size_t)(e1 & 0xFFFFu) * 128 + lane * 4];
        uint2 r2 = *(const uint2*)&g_qh[(size_t)(e2 & 0xFFFFu) * 128 + lane * 4];
        uint2 r3 = *(const uint2*)&g_qh[(size_t)(e3 & 0xFFFFu) * 128 + lane * 4];
        float ea0 = __half2float(__ushort_as_half((unsigned short)(e0 >> 16)));
        float ea1 = __half2float(__ushort_as_half((unsigned short)(e1 >> 16)));
        float ea2 = __half2float(__ushort_as_half((unsigned short)(e2 >> 16)));
        float ea3 = __half2float(__ushort_as_half((unsigned short)(e3 >> 16)));
        float2 a0 = __half22float2(*(const __half2*)&r0.x);
        float2 a1 = __half22float2(*(const __half2*)&r0.y);
        float2 b0 = __half22float2(*(const __half2*)&r1.x);
        float2 b1 = __half22float2(*(const __half2*)&r1.y);
        float2 c0 = __half22float2(*(const __half2*)&r2.x);
        float2 c1 = __half22float2(*(const __half2*)&r2.y);
        float2 d0 = __half22float2(*(const __half2*)&r3.x);
        float2 d1 = __half22float2(*(const __half2*)&r3.y);
        acc.x += fmaxf(fmaf(ea0, w.x, p.x + a0.x), 0.f) + fmaxf(fmaf(ea1, w.x, p.x + b0.x), 0.f)
               + fmaxf(fmaf(ea2, w.x, p.x + c0.x), 0.f) + fmaxf(fmaf(ea3, w.x, p.x + d0.x), 0.f);
        acc.y += fmaxf(fmaf(ea0, w.y, p.y + a0.y), 0.f) + fmaxf(fmaf(ea1, w.y, p.y + b0.y), 0.f)
               + fmaxf(fmaf(ea2, w.y, p.y + c0.y), 0.f) + fmaxf(fmaf(ea3, w.y, p.y + d0.y), 0.f);
        acc.z += fmaxf(fmaf(ea0, w.z, p.z + a1.x), 0.f) + fmaxf(fmaf(ea1, w.z, p.z + b1.x), 0.f)
               + fmaxf(fmaf(ea2, w.z, p.z + c1.x), 0.f) + fmaxf(fmaf(ea3, w.z, p.z + d1.x), 0.f);
        acc.w += fmaxf(fmaf(ea0, w.w, p.w + a1.y), 0.f) + fmaxf(fmaf(ea1, w.w, p.w + b1.y), 0.f)
               + fmaxf(fmaf(ea2, w.w, p.w + c1.y), 0.f) + fmaxf(fmaf(ea3, w.w, p.w + d1.y), 0.f);
    }
    for (; j < s1; j++) {
        uint32_t e = __ldg(&ep[j]);
        float ea = __half2float(__ushort_as_half((unsigned short)(e >> 16)));
        uint2 ra = *(const uint2*)&g_qh[(size_t)(e & 0xFFFFu) * 128 + lane * 4];
        float2 a0 = __half22float2(*(const __half2*)&ra.x);
        float2 a1 = __half22float2(*(const __half2*)&ra.y);
        acc.x += fmaxf(fmaf(ea, w.x, p.x + a0.x), 0.f);
        acc.y += fmaxf(fmaf(ea, w.y, p.y + a0.y), 0.f);
        acc.z += fmaxf(fmaf(ea, w.z, p.z + a1.x), 0.f);
        acc.w += fmaxf(fmaf(ea, w.w, p.w + a1.y), 0.f);
    }
    float inv = g_invdeg[node];
    __half2 h0 = __floats2half2_rn(acc.x * inv, acc.y * inv);
    __half2 h1 = __floats2half2_rn(acc.z * inv, acc.w * inv);
    uint2 u; u.x = *(uint32_t*)&h0; u.y = *(uint32_t*)&h1;
    *(uint2*)&g_Hh[(size_t)node * 128 + lane * 4] = u;
}

// ================= readout =================
__global__ void k_out(const float* __restrict__ W1, const float* __restrict__ b1,
                      const float* __restrict__ W2, const float* __restrict__ b2,
                      float* __restrict__ out, float invN) {
    __shared__ float gs[128];
    __shared__ float hs[128];
    int c = threadIdx.x;
    gs[c] = g_gvec[c] * invN;
    __syncthreads();
    float a = b1[c];
    #pragma unroll 8
    for (int k = 0; k < 128; k++) a = fmaf(gs[k], W1[k * 128 + c], a);
    hs[c] = fmaxf(a, 0.0f);
    __syncthreads();
    float o = b2[c];
    #pragma unroll 8
    for (int k = 0; k < 128; k++) o = fmaf(hs[k], W2[k * 128 + c], o);
    out[c] = o;
}

// ================= launch =================
extern "C" void kernel_launch(void* const* d_in, const int* in_sizes, int n_in,
                              void* d_out, int out_size) {
    const float* node_feat = (const float*)d_in[0];
    const float* edge_attr = (const float*)d_in[1];
    const float* enc_W  = (const float*)d_in[2];
    const float* enc_b  = (const float*)d_in[3];
    const float* mlp_W1 = (const float*)d_in[4];
    const float* mlp_b1 = (const float*)d_in[5];
    const float* mlp_W2 = (const float*)d_in[6];
    const float* mlp_b2 = (const float*)d_in[7];
    const float* upd_W1 = (const float*)d_in[8];
    const float* upd_b1 = (const float*)d_in[9];
    const float* upd_W2 = (const float*)d_in[10];
    const float* upd_b2 = (const float*)d_in[11];
    const float* ln_g   = (const float*)d_in[12];
    const float* ln_b   = (const float*)d_in[13];
    const float* out_W1 = (const float*)d_in[14];
    const float* out_b1 = (const float*)d_in[15];
    const float* out_W2 = (const float*)d_in[16];
    const float* out_b2 = (const float*)d_in[17];
    const int*   ei     = (const int*)d_in[18];

    const int N = NODES;
    const int E = EDGES;

    float *pbc, *pgate;
    __half *pxh, *pph, *pqh, *pHh, *pwTh;
    cudaGetSymbolAddress((void**)&pxh,   g_xh);
    cudaGetSymbolAddress((void**)&pph,   g_ph);
    cudaGetSymbolAddress((void**)&pqh,   g_qh);
    cudaGetSymbolAddress((void**)&pHh,   g_Hh);
    cudaGetSymbolAddress((void**)&pwTh,  g_wTh);
    cudaGetSymbolAddress((void**)&pbc,   g_bc);
    cudaGetSymbolAddress((void**)&pgate, g_gate);

    cudaFuncSetAttribute(k_gemm_pq, cudaFuncAttributeMaxDynamicSharedMemorySize, PQ_SMEM_BYTES);
    cudaFuncSetAttribute(k_updln<1>, cudaFuncAttributeMaxDynamicSharedMemorySize, UPD_SMEM_BYTES);
    cudaFuncSetAttribute(k_updln<2>, cudaFuncAttributeMaxDynamicSharedMemorySize, UPD_SMEM_BYTES);

    // one-time side stream + fork/join events (host resources only; no device mem)
    static cudaStream_t s2 = nullptr;
    static cudaEvent_t evF = nullptr, evJ = nullptr;
    if (s2 == nullptr) {
        cudaStreamCreateWithFlags(&s2, cudaStreamNonBlocking);
        cudaEventCreateWithFlags(&evF, cudaEventDisableTiming);
        cudaEventCreateWithFlags(&evJ, cudaEventDisableTiming);
    }

    // ---- fork: CSR chain on s2, prep chain on default stream ----
    cudaEventRecord(evF, 0);
    cudaStreamWaitEvent(s2, evF, 0);

    // s2: CSR build
    k_init<<<(N + 255) / 256, 256, 0, s2>>>(ei, N);
    k_count<<<(E + 255) / 256, 256, 0, s2>>>(ei, E);
    k_scan1<<<(N + 1023) / 1024, 1024, 0, s2>>>(N);
    k_scan3<<<(N + 255) / 256, 256, 0, s2>>>(N);
    k_scatter<<<(E + 255) / 256, 256, 0, s2>>>(ei, edge_attr, E);
    cudaEventRecord(evJ, s2);

    // main stream: encoder + weight prep + layer-0 PQ
    k_encode<<<(N * HID + 255) / 256, 256>>>(node_feat, enc_W, enc_b, N);
    k_repackT<<<NLAYER * 4 * 16384 / 256, 256>>>(mlp_W1, upd_W1, upd_W2);
    k_fuseW<<<dim3(128, NLAYER), 128>>>(mlp_W2, upd_W1, mlp_b2);

    const int gt64 = (N + 63) / 64;
    k_gemm_pq<<<dim3(gt64, 2), 256, PQ_SMEM_BYTES>>>(
        pxh, pwTh + 0 * 16384, pwTh + 1 * 16384, mlp_b1, pph, pqh, N);

    // join: aggr needs CSR + P/Q
    cudaStreamWaitEvent(0, evJ, 0);

    for (int l = 0; l < NLAYER; l++) {
        const float* W1l = mlp_W1 + (size_t)l * 257 * 128;
        __half* wl = pwTh + (size_t)l * 5 * 16384;

        k_aggr<<<(N + 7) / 8, 256>>>(W1l + 256 * 128, N);

        if (l < NLAYER - 1) {
            __half* wn = pwTh + (size_t)(l + 1) * 5 * 16384;
            k_updln<1><<<gt64, 256, UPD_SMEM_BYTES>>>(
                pxh, pHh, wl + 2 * 16384, wl + 4 * 16384, wl + 3 * 16384,
                wn + 0 * 16384, wn + 1 * 16384,
                upd_b1 + l * 128, pbc + l * 128, pgate,
                upd_b2 + l * 128, ln_g + l * 128, ln_b + l * 128,
                mlp_b1 + (l + 1) * 128,
                pxh, pph, pqh, N);
        } else {
            k_updln<2><<<gt64, 256, UPD_SMEM_BYTES>>>(
                pxh, pHh, wl + 2 * 16384, wl + 4 * 16384, wl + 3 * 16384,
                nullptr, nullptr,
                upd_b1 + l * 128, pbc + l * 128, pgate,
                upd_b2 + l * 128, ln_g + l * 128, ln_b + l * 128,
                nullptr,
                pxh, pph, pqh, N);
        }
    }

    k_out<<<1, 128>>>(out_W1, out_b1, out_W2, out_b2, (float*)d_out, 1.0f / (float)N);
}